// round 11
// baseline (speedup 1.0000x reference)
#include <cuda_runtime.h>
#include <cstdint>

typedef unsigned long long ull;

#define B_   32
#define NH_  8
#define NN_  1024
#define NS_  21
#define NT_  1003
#define D_   128
#define KD_  16
#define HB_  (NH_*B_)

// NORM * log2(e) folded into query projections so softmax uses raw ex2.
#define QSCALE 0.36067376022224085f

#define CHUNK 128
#define KSTR  20    // K smem row stride (floats): conflict-free score-frag loads
#define VSTR  24    // V smem row stride (floats): conflict-free PV-frag loads
#define XSTR  132   // x smem row stride in proj
#define BSTR  132   // Wcat smem row stride in proj (132 needed: staging writes)

// ---------------- scratch (device globals; no allocation allowed) ----------
__device__ float g_Qtt[HB_*NT_*KD_];
__device__ float g_Qts[HB_*NT_*KD_];
__device__ float g_Kc [HB_*NT_*KD_];
__device__ float g_Vc [HB_*NT_*KD_];
__device__ float g_Qst[HB_*NS_*KD_];
__device__ float g_Ks [HB_*NS_*KD_];
__device__ float g_Vs [HB_*NS_*KD_];
__device__ float g_heads[B_*NN_*NH_*KD_];   // layout [b][n][h][k]

// ---------------- helpers ---------------------------------------------------
__device__ __forceinline__ ull pack2(float lo, float hi){
  ull r; asm("mov.b64 %0, {%1,%2};" : "=l"(r) : "f"(lo), "f"(hi)); return r;
}
__device__ __forceinline__ void unpack2(ull v, float& lo, float& hi){
  asm("mov.b64 {%0,%1}, %2;" : "=f"(lo), "=f"(hi) : "l"(v));
}
__device__ __forceinline__ ull ffma2(ull a, ull b, ull c){
  ull d; asm("fma.rn.f32x2 %0, %1, %2, %3;" : "=l"(d) : "l"(a), "l"(b), "l"(c)); return d;
}
__device__ __forceinline__ float ex2f(float x){
  float r; asm("ex2.approx.f32 %0, %1;" : "=f"(r) : "f"(x)); return r;
}
__device__ __forceinline__ uint32_t tf32r(float f){
  uint32_t u; asm("cvt.rna.tf32.f32 %0, %1;" : "=r"(u) : "f"(f)); return u;
}
__device__ __forceinline__ float tf32rf(float f){ return __uint_as_float(tf32r(f)); }

__device__ __forceinline__ void cp_async16(void* s, const void* g){
  unsigned sa = (unsigned)__cvta_generic_to_shared(s);
  asm volatile("cp.async.cg.shared.global [%0], [%1], 16;" :: "r"(sa), "l"(g));
}
__device__ __forceinline__ void cp_commit(){ asm volatile("cp.async.commit_group;"); }
template<int N> __device__ __forceinline__ void cp_wait(){
  asm volatile("cp.async.wait_group %0;" :: "n"(N) : "memory");
}

// tf32 MMA: D(16x8) += A(16x8,row) * B(8x8,col)
__device__ __forceinline__ void mma8(float& d0, float& d1, float& d2, float& d3,
    uint32_t a0, uint32_t a1, uint32_t a2, uint32_t a3, uint32_t b0, uint32_t b1)
{
  asm("mma.sync.aligned.m16n8k8.row.col.f32.tf32.tf32.f32 "
      "{%0,%1,%2,%3},{%4,%5,%6,%7},{%8,%9},{%0,%1,%2,%3};"
      : "+f"(d0), "+f"(d1), "+f"(d2), "+f"(d3)
      : "r"(a0), "r"(a1), "r"(a2), "r"(a3), "r"(b0), "r"(b1));
}

// Load Q A-fragments for 2 k-steps (head_dim 16). rA,rB pre-clamped row indices.
__device__ __forceinline__ void loadQ(const float* Qb, int rA, int rB, int tig,
                                      uint32_t a[2][4])
{
  #pragma unroll
  for (int ks = 0; ks < 2; ks++){
    a[ks][0] = __float_as_uint(Qb[(size_t)rA*KD_ + tig     + 8*ks]);
    a[ks][1] = __float_as_uint(Qb[(size_t)rB*KD_ + tig     + 8*ks]);
    a[ks][2] = __float_as_uint(Qb[(size_t)rA*KD_ + tig + 4 + 8*ks]);
    a[ks][3] = __float_as_uint(Qb[(size_t)rB*KD_ + tig + 4 + 8*ks]);
  }
}

// One 8-key step (used for the 21-key station softmax only).
template<int MASK>
__device__ __forceinline__ void attn_step(
    const float* __restrict__ Ks, const float* __restrict__ Vs,
    const uint32_t (&aQ)[2][4], float (&o)[2][4], float (&ls)[4],
    int n8, int g, int tig, int lane, int nvalid)
{
  float c0 = 0.f, c1 = 0.f, c2 = 0.f, c3 = 0.f;
  const float* kp = Ks + (n8 + g)*KSTR + tig;
  {
    uint32_t b0 = __float_as_uint(kp[0]),  b1 = __float_as_uint(kp[4]);
    mma8(c0,c1,c2,c3, aQ[0][0],aQ[0][1],aQ[0][2],aQ[0][3], b0, b1);
    uint32_t b2 = __float_as_uint(kp[8]),  b3 = __float_as_uint(kp[12]);
    mma8(c0,c1,c2,c3, aQ[1][0],aQ[1][1],aQ[1][2],aQ[1][3], b2, b3);
  }
  float p0 = ex2f(c0), p1 = ex2f(c1), p2 = ex2f(c2), p3 = ex2f(c3);
  if (MASK){
    int col = n8 + tig*2;
    if (col     >= nvalid){ p0 = 0.f; p2 = 0.f; }
    if (col + 1 >= nvalid){ p1 = 0.f; p3 = 0.f; }
  }
  uint32_t u0 = tf32r(p0), u1 = tf32r(p1), u2 = tf32r(p2), u3 = tf32r(p3);
  int src  = (lane & 28) | (tig >> 1);
  int src2 = src + 2;
  uint32_t ev0 = __shfl_sync(0xffffffffu, u0, src ), od0 = __shfl_sync(0xffffffffu, u1, src );
  uint32_t ev1 = __shfl_sync(0xffffffffu, u2, src ), od1 = __shfl_sync(0xffffffffu, u3, src );
  uint32_t ev2 = __shfl_sync(0xffffffffu, u0, src2), od2 = __shfl_sync(0xffffffffu, u1, src2);
  uint32_t ev3 = __shfl_sync(0xffffffffu, u2, src2), od3 = __shfl_sync(0xffffffffu, u3, src2);
  bool odd = (tig & 1);
  uint32_t pa0 = odd ? od0 : ev0;
  uint32_t pa1 = odd ? od1 : ev1;
  uint32_t pa2 = odd ? od2 : ev2;
  uint32_t pa3 = odd ? od3 : ev3;
  const uint32_t one = 0x3f800000u;          // 1.0f (tf32-exact)
  mma8(ls[0], ls[1], ls[2], ls[3], pa0, pa1, pa2, pa3, one, one);
  #pragma unroll
  for (int nt = 0; nt < 2; nt++){
    uint32_t vb0 = __float_as_uint(Vs[(n8 + tig    )*VSTR + nt*8 + g]);
    uint32_t vb1 = __float_as_uint(Vs[(n8 + tig + 4)*VSTR + nt*8 + g]);
    mma8(o[nt][0], o[nt][1], o[nt][2], o[nt][3], pa0, pa1, pa2, pa3, vb0, vb1);
  }
}

// 16-key step: two independent 8-key halves fused for ILP — all 4 score MMAs
// issue back-to-back, the 8 ex2 / 16 shfl of one half hide behind the other's
// MMAs, breaking the per-step MMA->ex2->shfl->MMA serial chain.
template<int MASK>
__device__ __forceinline__ void attn_step2(
    const float* __restrict__ Ks, const float* __restrict__ Vs,
    const uint32_t (&aQ)[2][4], float (&o)[2][4], float (&ls)[4],
    int n8, int g, int tig, int lane, int nvalid)
{
  float cA0=0.f,cA1=0.f,cA2=0.f,cA3=0.f, cB0=0.f,cB1=0.f,cB2=0.f,cB3=0.f;
  const float* kpA = Ks + (n8 + g)*KSTR + tig;
  const float* kpB = kpA + 8*KSTR;
  {
    uint32_t a0 = __float_as_uint(kpA[0]),  a1 = __float_as_uint(kpA[4]);
    uint32_t a2 = __float_as_uint(kpA[8]),  a3 = __float_as_uint(kpA[12]);
    uint32_t b0 = __float_as_uint(kpB[0]),  b1 = __float_as_uint(kpB[4]);
    uint32_t b2 = __float_as_uint(kpB[8]),  b3 = __float_as_uint(kpB[12]);
    mma8(cA0,cA1,cA2,cA3, aQ[0][0],aQ[0][1],aQ[0][2],aQ[0][3], a0, a1);
    mma8(cB0,cB1,cB2,cB3, aQ[0][0],aQ[0][1],aQ[0][2],aQ[0][3], b0, b1);
    mma8(cA0,cA1,cA2,cA3, aQ[1][0],aQ[1][1],aQ[1][2],aQ[1][3], a2, a3);
    mma8(cB0,cB1,cB2,cB3, aQ[1][0],aQ[1][1],aQ[1][2],aQ[1][3], b2, b3);
  }
  float pA0 = ex2f(cA0), pA1 = ex2f(cA1), pA2 = ex2f(cA2), pA3 = ex2f(cA3);
  float pB0 = ex2f(cB0), pB1 = ex2f(cB1), pB2 = ex2f(cB2), pB3 = ex2f(cB3);
  if (MASK){
    int colA = n8 + tig*2, colB = colA + 8;
    if (colA     >= nvalid){ pA0 = 0.f; pA2 = 0.f; }
    if (colA + 1 >= nvalid){ pA1 = 0.f; pA3 = 0.f; }
    if (colB     >= nvalid){ pB0 = 0.f; pB2 = 0.f; }
    if (colB + 1 >= nvalid){ pB1 = 0.f; pB3 = 0.f; }
  }
  uint32_t uA0 = tf32r(pA0), uA1 = tf32r(pA1), uA2 = tf32r(pA2), uA3 = tf32r(pA3);
  uint32_t uB0 = tf32r(pB0), uB1 = tf32r(pB1), uB2 = tf32r(pB2), uB3 = tf32r(pB3);
  int src  = (lane & 28) | (tig >> 1);
  int src2 = src + 2;
  uint32_t eA0 = __shfl_sync(0xffffffffu, uA0, src ), oA0 = __shfl_sync(0xffffffffu, uA1, src );
  uint32_t eA1 = __shfl_sync(0xffffffffu, uA2, src ), oA1 = __shfl_sync(0xffffffffu, uA3, src );
  uint32_t eA2 = __shfl_sync(0xffffffffu, uA0, src2), oA2 = __shfl_sync(0xffffffffu, uA1, src2);
  uint32_t eA3 = __shfl_sync(0xffffffffu, uA2, src2), oA3 = __shfl_sync(0xffffffffu, uA3, src2);
  uint32_t eB0 = __shfl_sync(0xffffffffu, uB0, src ), oB0 = __shfl_sync(0xffffffffu, uB1, src );
  uint32_t eB1 = __shfl_sync(0xffffffffu, uB2, src ), oB1 = __shfl_sync(0xffffffffu, uB3, src );
  uint32_t eB2 = __shfl_sync(0xffffffffu, uB0, src2), oB2 = __shfl_sync(0xffffffffu, uB1, src2);
  uint32_t eB3 = __shfl_sync(0xffffffffu, uB2, src2), oB3 = __shfl_sync(0xffffffffu, uB3, src2);
  bool odd = (tig & 1);
  uint32_t qA0 = odd ? oA0 : eA0, qA1 = odd ? oA1 : eA1;
  uint32_t qA2 = odd ? oA2 : eA2, qA3 = odd ? oA3 : eA3;
  uint32_t qB0 = odd ? oB0 : eB0, qB1 = odd ? oB1 : eB1;
  uint32_t qB2 = odd ? oB2 : eB2, qB3 = odd ? oB3 : eB3;
  const uint32_t one = 0x3f800000u;
  mma8(ls[0], ls[1], ls[2], ls[3], qA0, qA1, qA2, qA3, one, one);
  mma8(ls[0], ls[1], ls[2], ls[3], qB0, qB1, qB2, qB3, one, one);
  #pragma unroll
  for (int nt = 0; nt < 2; nt++){
    uint32_t vA0 = __float_as_uint(Vs[(n8 + tig     )*VSTR + nt*8 + g]);
    uint32_t vA1 = __float_as_uint(Vs[(n8 + tig +  4)*VSTR + nt*8 + g]);
    uint32_t vB0 = __float_as_uint(Vs[(n8 + tig +  8)*VSTR + nt*8 + g]);
    uint32_t vB1 = __float_as_uint(Vs[(n8 + tig + 12)*VSTR + nt*8 + g]);
    mma8(o[nt][0], o[nt][1], o[nt][2], o[nt][3], qA0, qA1, qA2, qA3, vA0, vA1);
    mma8(o[nt][0], o[nt][1], o[nt][2], o[nt][3], qB0, qB1, qB2, qB3, vB0, vB1);
  }
}

// Cooperative chunk staging: 128 keys x 16 floats of K and V (256 threads).
__device__ __forceinline__ void stage_chunk(float* sKb, float* sVb,
    const float* __restrict__ Kg, const float* __restrict__ Vg, int kbase, int tid)
{
  #pragma unroll
  for (int i = 0; i < 2; i++){
    int f4  = tid + i*256;
    int row = f4 >> 2, qq = f4 & 3;
    int gr  = kbase + row;
    if (gr < NT_){
      cp_async16(sKb + row*KSTR + qq*4, Kg + (size_t)gr*KD_ + qq*4);
      cp_async16(sVb + row*VSTR + qq*4, Vg + (size_t)gr*KD_ + qq*4);
    }
  }
}

// ====================== Kernel 1: all projections ==========================
// blockIdx.x < 16 : token tile of 64 rows. Register-tiled fp32 f32x2 GEMM
//                   X[64,128] @ Wcat[128,128] per projection. Exact fp32 fma
//                   (tf32 proj FAILS rel-err: R7).
// blockIdx.x == 16: station projections (21 rows, scalar).
__global__ __launch_bounds__(256, 2) void k_proj(
    const float* __restrict__ q, const float* __restrict__ h,
    const float* __restrict__ Wqtt, const float* __restrict__ Wqts,
    const float* __restrict__ Wk, const float* __restrict__ Wv,
    const float* __restrict__ Wqst, const float* __restrict__ Wks,
    const float* __restrict__ Wvs)
{
  extern __shared__ float sm[];
  int b  = blockIdx.y;
  int tid = threadIdx.x;

  if (blockIdx.x == 16){
    float* sxq = sm;                 // 21*128
    float* sxh = sm + NS_*D_;
    float* sw  = sm + 2*NS_*D_;      // 128*16
    for (int idx = tid; idx < NS_*D_/4; idx += 256){
      int row = idx >> 5, d4 = idx & 31;
      size_t goff = ((size_t)(b*NN_ + row))*D_ + d4*4;
      ((float4*)sxq)[idx] = *(const float4*)(q + goff);
      ((float4*)sxh)[idx] = *(const float4*)(h + goff);
    }
    const float* Wp[3] = {Wqst, Wks, Wvs};
    for (int p = 0; p < 3; p++){
      const float* src = (p == 0) ? sxq : sxh;
      float scale = (p == 0) ? QSCALE : 1.0f;
      float* Dst = (p == 0) ? g_Qst : (p == 1 ? g_Ks : g_Vs);
      for (int hh = 0; hh < NH_; hh++){
        __syncthreads();
        const float* wp = Wp[p] + hh*D_*KD_;
        for (int idx = tid; idx < D_*KD_; idx += 256) sw[idx] = wp[idx]*scale;
        __syncthreads();
        for (int o = tid; o < NS_*KD_; o += 256){
          int s = o >> 4, k = o & 15;
          float a = 0.f;
          #pragma unroll 8
          for (int d = 0; d < D_; d++) a += src[s*D_ + d] * sw[d*KD_ + k];
          Dst[((size_t)(hh*B_ + b)*NS_ + s)*KD_ + k] = tf32rf(a);
        }
      }
    }
    return;
  }

  // ---------------- token projections: register-tiled GEMM ----------------
  float* sx = sm;                    // 64*XSTR   (x rows: q then h)
  float* sw = sm + 64*XSTR;          // 128*BSTR  (Wcat[d][hh*16+k], k-contig)

  int r0 = blockIdx.x * 64;
  int rg = tid >> 4, cg = tid & 15;            // 4-row group, 8-col group
  int hh = cg >> 1, khalf = (cg & 1)*8;

  const float* Xs[2] = {q, h};
  const float* Wp[4] = {Wqtt, Wqts, Wk, Wv};
  float* Dp[4]; Dp[0]=g_Qtt; Dp[1]=g_Qts; Dp[2]=g_Kc; Dp[3]=g_Vc;

  for (int ph = 0; ph < 2; ph++){
    const float* xs = Xs[ph];
    #pragma unroll
    for (int i = 0; i < 8; i++){
      int idx = tid + i*256;
      int row = idx >> 5, d4 = idx & 31;
      int t = r0 + row; if (t > NT_-1) t = NT_-1;
      ((float4*)(sx + row*XSTR))[d4] =
          *(const float4*)(xs + ((size_t)(b*NN_ + NS_ + t))*D_ + d4*4);
    }
    for (int pp = 0; pp < 2; pp++){
      int p = ph*2 + pp;
      float scale = (p < 2) ? QSCALE : 1.0f;
      const float* wg = Wp[p];
      #pragma unroll
      for (int i = 0; i < 16; i++){
        int idx = tid + i*256;              // 4096 float4
        int d = idx & 127, hk = idx >> 7;
        int whh = hk >> 2, k4 = hk & 3;
        float4 v = *(const float4*)(wg + whh*(D_*KD_) + d*KD_ + k4*4);
        v.x *= scale; v.y *= scale; v.z *= scale; v.w *= scale;
        *(float4*)(sw + d*BSTR + whh*16 + k4*4) = v;
      }
      __syncthreads();

      ull acc[4][4];
      #pragma unroll
      for (int i = 0; i < 4; i++)
        #pragma unroll
        for (int j = 0; j < 4; j++) acc[i][j] = 0ull;

      const float* Ab = sx + rg*4*XSTR;
      const float* Bb = sw + cg*8;
      #pragma unroll 2
      for (int kg = 0; kg < 32; kg++){
        float4 a[4];
        #pragma unroll
        for (int i = 0; i < 4; i++)
          a[i] = *(const float4*)(Ab + i*XSTR + kg*4);
        #pragma unroll
        for (int kk = 0; kk < 4; kk++){
          ulonglong2 bv0 = *(const ulonglong2*)(Bb + (kg*4 + kk)*BSTR);
          ulonglong2 bv1 = *(const ulonglong2*)(Bb + (kg*4 + kk)*BSTR + 4);
          #pragma unroll
          for (int i = 0; i < 4; i++){
            float av = (&a[i].x)[kk];
            ull ap = pack2(av, av);
            acc[i][0] = ffma2(ap, bv0.x, acc[i][0]);
            acc[i][1] = ffma2(ap, bv0.y, acc[i][1]);
            acc[i][2] = ffma2(ap, bv1.x, acc[i][2]);
            acc[i][3] = ffma2(ap, bv1.y, acc[i][3]);
          }
        }
      }

      float* dst = Dp[p] + ((size_t)(hh*B_ + b))*NT_*KD_ + khalf;
      #pragma unroll
      for (int i = 0; i < 4; i++){
        int t = r0 + rg*4 + i;
        if (t < NT_){
          float f0,f1,f2,f3,f4,f5,f6,f7;
          unpack2(acc[i][0], f0, f1);
          unpack2(acc[i][1], f2, f3);
          unpack2(acc[i][2], f4, f5);
          unpack2(acc[i][3], f6, f7);
          float4 v0 = make_float4(tf32rf(f0), tf32rf(f1), tf32rf(f2), tf32rf(f3));
          float4 v1 = make_float4(tf32rf(f4), tf32rf(f5), tf32rf(f6), tf32rf(f7));
          *(float4*)(dst + (size_t)t*KD_)     = v0;
          *(float4*)(dst + (size_t)t*KD_ + 4) = v1;
        }
      }
      __syncthreads();
    }
  }
}

// ====================== Kernel 2: all attention ============================
// blockIdx.x < 8 : token-query path (128-query tile, warp = 16 q x all keys).
// blockIdx.x == 8: station-query path (warp = 16 q-rows x key stripe).
// No online max (QSCALE folds NORM*log2e; scores bounded, raw ex2 safe).
// Row sums fall out of the ones-MMA D-fragments already fully reduced.
// 16-key fused steps + 2 blocks/SM for latency hiding.
__global__ __launch_bounds__(256, 2) void k_attn()
{
  extern __shared__ float dsm[];
  float* sK0 = dsm;                                   // [2][128*KSTR]
  float* sV0 = dsm + 2*CHUNK*KSTR;                    // [2][128*VSTR]
  float* sKs = dsm + 2*CHUNK*KSTR + 2*CHUNK*VSTR;     // token: [24*KSTR]
  float* sVs = sKs + 24*KSTR;                         // token: [24*VSTR]
  float* red = dsm + 2*CHUNK*KSTR + 2*CHUNK*VSTR;     // station: [8*32*10]

  int b = blockIdx.y, hh = blockIdx.z;
  int tid = threadIdx.x;
  int w = tid >> 5, lane = tid & 31;
  int g = lane >> 2, tig = lane & 3;
  size_t hb = (size_t)(hh*B_ + b);
  const float* Kg = g_Kc + hb*NT_*KD_;
  const float* Vg = g_Vc + hb*NT_*KD_;
  const int nch = (NT_ + CHUNK - 1)/CHUNK;   // 8

  if (blockIdx.x < 8){
    // ======== token-query path ========
    int qrow = blockIdx.x * 128 + w*16;
    int rA = min(qrow + g,     NT_-1);
    int rB = min(qrow + g + 8, NT_-1);

    // zero station pad rows (21..23) so pad scores are finite then masked
    for (int i = tid; i < 3*KSTR; i += 256) sKs[21*KSTR + i] = 0.f;
    for (int i = tid; i < 3*VSTR; i += 256) sVs[21*VSTR + i] = 0.f;
    // group 1: station K/V
    if (tid < 96){
      int row = tid >> 2, qq = tid & 3;
      if (row < NS_){
        cp_async16(sKs + row*KSTR + qq*4, g_Ks + (hb*NS_ + row)*KD_ + qq*4);
        cp_async16(sVs + row*VSTR + qq*4, g_Vs + (hb*NS_ + row)*KD_ + qq*4);
      }
    }
    cp_commit();
    // group 2: token chunk 0
    stage_chunk(sK0, sV0, Kg, Vg, 0, tid);
    cp_commit();

    uint32_t aT[2][4];
    loadQ(g_Qtt + hb*NT_*KD_, rA, rB, tig, aT);

    // ---- station prologue: full mini-softmax, normalized into os ----
    float os[2][4] = {{0,0,0,0},{0,0,0,0}};
    {
      uint32_t aS[2][4];
      loadQ(g_Qts + hb*NT_*KD_, rA, rB, tig, aS);
      cp_wait<1>();          // group 1 (station) done
      __syncthreads();
      float lsS[4] = {0,0,0,0};
      attn_step2<0>(sKs, sVs, aS, os, lsS, 0,  g, tig, lane, 0);
      attn_step<1> (sKs, sVs, aS, os, lsS, 16, g, tig, lane, NS_);
      float isa = 1.f/lsS[0], isb = 1.f/lsS[2];
      #pragma unroll
      for (int nt = 0; nt < 2; nt++){
        os[nt][0] *= isa; os[nt][1] *= isa;
        os[nt][2] *= isb; os[nt][3] *= isb;
      }
    }

    // ---- token mainloop (16-key fused steps) ----
    float ot[2][4] = {{0,0,0,0},{0,0,0,0}};
    float ls[4] = {0,0,0,0};
    for (int c = 0; c < nch; c++){
      if (c + 1 < nch){
        int nb = (c+1) & 1;
        stage_chunk(sK0 + nb*CHUNK*KSTR, sV0 + nb*CHUNK*VSTR, Kg, Vg, (c+1)*CHUNK, tid);
        cp_commit();
        cp_wait<1>();
      } else {
        cp_wait<0>();
      }
      __syncthreads();
      const float* Ks = sK0 + (c&1)*CHUNK*KSTR;
      const float* Vs = sV0 + (c&1)*CHUNK*VSTR;
      int nv = min(CHUNK, NT_ - c*CHUNK);
      int nf = nv >> 4;
      #pragma unroll 2
      for (int n = 0; n < nf; n++)
        attn_step2<0>(Ks, Vs, aT, ot, ls, n*16, g, tig, lane, 0);
      if (nv & 15)
        attn_step2<1>(Ks, Vs, aT, ot, ls, nf*16, g, tig, lane, nv);
      __syncthreads();
    }

    float ita = 1.f/ls[0], itb = 1.f/ls[2];   // ones-MMA: already full row sums
    int row0 = qrow + g, row1 = qrow + g + 8;
    #pragma unroll
    for (int nt = 0; nt < 2; nt++){
      if (row0 < NT_){
        float2 v; v.x = ot[nt][0]*ita + os[nt][0];
                  v.y = ot[nt][1]*ita + os[nt][1];
        *(float2*)(g_heads + ((size_t)(b*NN_ + NS_ + row0)*NH_ + hh)*KD_ + nt*8 + 2*tig) = v;
      }
      if (row1 < NT_){
        float2 v; v.x = ot[nt][2]*itb + os[nt][2];
                  v.y = ot[nt][3]*itb + os[nt][3];
        *(float2*)(g_heads + ((size_t)(b*NN_ + NS_ + row1)*NH_ + hh)*KD_ + nt*8 + 2*tig) = v;
      }
    }
  } else {
    // ======== station-query path ========
    int rt = w & 1, s = w >> 1;        // 2 q-row-tiles x 4 key stripes (32 keys)
    int rA = min(rt*16 + g,     NS_-1);
    int rB = min(rt*16 + g + 8, NS_-1);
    uint32_t aQ[2][4];
    loadQ(g_Qst + hb*NS_*KD_, rA, rB, tig, aQ);

    float o[2][4] = {{0,0,0,0},{0,0,0,0}};
    float ls[4] = {0,0,0,0};

    stage_chunk(sK0, sV0, Kg, Vg, 0, tid);
    cp_commit();
    for (int c = 0; c < nch; c++){
      if (c + 1 < nch){
        int nb = (c+1) & 1;
        stage_chunk(sK0 + nb*CHUNK*KSTR, sV0 + nb*CHUNK*VSTR, Kg, Vg, (c+1)*CHUNK, tid);
        cp_commit();
        cp_wait<1>();
      } else {
        cp_wait<0>();
      }
      __syncthreads();
      const float* Ks = sK0 + (c&1)*CHUNK*KSTR;
      const float* Vs = sV0 + (c&1)*CHUNK*VSTR;
      int nv = min(CHUNK, NT_ - c*CHUNK);
      #pragma unroll
      for (int j = 0; j < 2; j++){
        int n8 = s*32 + j*16;
        if (n8 + 16 <= nv)
          attn_step2<0>(Ks, Vs, aQ, o, ls, n8, g, tig, lane, 0);
        else if (n8 < nv)
          attn_step2<1>(Ks, Vs, aQ, o, ls, n8, g, tig, lane, nv);
      }
      __syncthreads();
    }

    float* rp = red + (w*32 + lane)*10;
    rp[0]=o[0][0]; rp[1]=o[0][1]; rp[2]=o[0][2]; rp[3]=o[0][3];
    rp[4]=o[1][0]; rp[5]=o[1][1]; rp[6]=o[1][2]; rp[7]=o[1][3];
    rp[8]=ls[0]; rp[9]=ls[2];
    __syncthreads();
    if (w < 2){
      float la = ls[0], lb = ls[2];
      #pragma unroll
      for (int ss = 1; ss < 4; ss++){
        float* qp = red + ((w + 2*ss)*32 + lane)*10;
        o[0][0]+=qp[0]; o[0][1]+=qp[1]; o[0][2]+=qp[2]; o[0][3]+=qp[3];
        o[1][0]+=qp[4]; o[1][1]+=qp[5]; o[1][2]+=qp[6]; o[1][3]+=qp[7];
        la += qp[8]; lb += qp[9];
      }
      float ia = 1.f/la, ib = 1.f/lb;
      int r0 = rt*16 + g, r1 = r0 + 8;
      #pragma unroll
      for (int nt = 0; nt < 2; nt++){
        if (r0 < NS_){
          float2 v; v.x = o[nt][0]*ia; v.y = o[nt][1]*ia;
          *(float2*)(g_heads + ((size_t)(b*NN_ + r0)*NH_ + hh)*KD_ + nt*8 + 2*tig) = v;
        }
        if (r1 < NS_){
          float2 v; v.x = o[nt][2]*ib; v.y = o[nt][3]*ib;
          *(float2*)(g_heads + ((size_t)(b*NN_ + r1)*NH_ + hh)*KD_ + nt*8 + 2*tig) = v;
        }
      }
    }
  }
}

// ================ Kernel 3: output GEMM (fp32 f32x2, value path) ===========
__global__ __launch_bounds__(256, 2) void k_out(
    const float* __restrict__ Wout, float* __restrict__ out)
{
  extern __shared__ float sm[];
  float* sA  = sm;              // 64*128
  float* sWt = sm + 64*D_;      // 128*132 transposed
  int m0 = blockIdx.x * 64;
  int tid = threadIdx.x;
  for (int idx = tid; idx < 64*32; idx += 256){
    int r = idx >> 5, d4 = idx & 31;
    ((float4*)(sA + r*D_))[d4] = ((const float4*)(g_heads + (size_t)(m0 + r)*D_))[d4];
  }
  for (int idx = tid; idx < D_*D_; idx += 256){
    int c = idx >> 7, e = idx & 127;
    sWt[e*132 + c] = Wout[idx];
  }
  __syncthreads();
  int rg = tid >> 4, cg = tid & 15;
  ull acc2[4][8];
  #pragma unroll
  for (int i = 0; i < 4; i++)
    #pragma unroll
    for (int e = 0; e < 8; e++) acc2[i][e] = 0ull;
  #pragma unroll 2
  for (int d4 = 0; d4 < 32; d4++){
    ulonglong2 a[4];
    #pragma unroll
    for (int i = 0; i < 4; i++)
      a[i] = *(const ulonglong2*)(sA + (rg*4 + i)*D_ + d4*4);
    #pragma unroll
    for (int e = 0; e < 8; e++){
      ulonglong2 wv = *(const ulonglong2*)(sWt + (cg*8 + e)*132 + d4*4);
      #pragma unroll
      for (int i = 0; i < 4; i++){
        acc2[i][e] = ffma2(a[i].x, wv.x, acc2[i][e]);
        acc2[i][e] = ffma2(a[i].y, wv.y, acc2[i][e]);
      }
    }
  }
  #pragma unroll
  for (int i = 0; i < 4; i++){
    #pragma unroll
    for (int e = 0; e < 8; e++){
      float lo, hi; unpack2(acc2[i][e], lo, hi);
      out[(size_t)(m0 + rg*4 + i)*D_ + cg*8 + e] = lo + hi;
    }
  }
}

// ===========================================================================
extern "C" void kernel_launch(void* const* d_in, const int* in_sizes, int n_in,
                              void* d_out, int out_size)
{
  const float* q     = (const float*)d_in[0];
  const float* h     = (const float*)d_in[1];
  const float* Wq_ts = (const float*)d_in[2];   // W_query_custom    -> Q_ts
  const float* Wq_tt = (const float*)d_in[3];   // W_query_custom_1  -> Q_tt
  const float* Wk_c  = (const float*)d_in[4];   // W_key_custom
  const float* Wv_c  = (const float*)d_in[5];   // W_val_custom
  const float* Wq_st = (const float*)d_in[6];   // W_query_charge_1  -> Q_st
  const float* Wk_s  = (const float*)d_in[7];   // W_key_charge
  const float* Wv_s  = (const float*)d_in[8];   // W_val_charge
  const float* Wout  = (const float*)d_in[9];
  float* out = (float*)d_out;

  int smem1 = (64*XSTR + 128*BSTR)*(int)sizeof(float);   // 101376 B
  cudaFuncSetAttribute(k_proj, cudaFuncAttributeMaxDynamicSharedMemorySize, smem1);
  int smemA = (2*CHUNK*KSTR + 2*CHUNK*VSTR + 8*32*10)*(int)sizeof(float);
  cudaFuncSetAttribute(k_attn, cudaFuncAttributeMaxDynamicSharedMemorySize, smemA);
  int smem5 = (64*D_ + D_*132)*(int)sizeof(float);
  cudaFuncSetAttribute(k_out, cudaFuncAttributeMaxDynamicSharedMemorySize, smem5);

  k_proj<<<dim3(17, 32), 256, smem1>>>(q, h, Wq_tt, Wq_ts, Wk_c, Wv_c,
                                       Wq_st, Wk_s, Wv_s);
  k_attn<<<dim3(9, 32, 8), 256, smemA>>>();
  k_out<<<512, 256, smem5>>>(Wout, out);
}

// round 13
// speedup vs baseline: 1.0583x; 1.0583x over previous
#include <cuda_runtime.h>
#include <cstdint>

typedef unsigned long long ull;

#define B_   32
#define NH_  8
#define NN_  1024
#define NS_  21
#define NT_  1003
#define D_   128
#define KD_  16
#define HB_  (NH_*B_)

// NORM * log2(e) folded into query projections so softmax uses raw ex2.
#define QSCALE 0.36067376022224085f

#define CHUNK 128
#define KSTR  20    // K smem row stride (floats): conflict-free score-frag loads
#define VSTR  24    // V smem row stride (floats): conflict-free PV-frag loads
#define XSTR  132   // x smem row stride in proj
#define BSTR  132   // Wcat smem row stride in proj

// ---------------- scratch (device globals; no allocation allowed) ----------
__device__ float g_Qtt[HB_*NT_*KD_];
__device__ float g_Qts[HB_*NT_*KD_];
__device__ float g_Kc [HB_*NT_*KD_];
__device__ float g_Vc [HB_*NT_*KD_];
__device__ float g_Qst[HB_*NS_*KD_];
__device__ float g_Ks [HB_*NS_*KD_];
__device__ float g_Vs [HB_*NS_*KD_];
__device__ float g_heads[B_*NN_*NH_*KD_];   // layout [b][n][h][k]

// ---------------- helpers ---------------------------------------------------
__device__ __forceinline__ ull pack2(float lo, float hi){
  ull r; asm("mov.b64 %0, {%1,%2};" : "=l"(r) : "f"(lo), "f"(hi)); return r;
}
__device__ __forceinline__ void unpack2(ull v, float& lo, float& hi){
  asm("mov.b64 {%0,%1}, %2;" : "=f"(lo), "=f"(hi) : "l"(v));
}
__device__ __forceinline__ ull ffma2(ull a, ull b, ull c){
  ull d; asm("fma.rn.f32x2 %0, %1, %2, %3;" : "=l"(d) : "l"(a), "l"(b), "l"(c)); return d;
}
__device__ __forceinline__ float ex2f(float x){
  float r; asm("ex2.approx.f32 %0, %1;" : "=f"(r) : "f"(x)); return r;
}
__device__ __forceinline__ uint32_t tf32r(float f){
  uint32_t u; asm("cvt.rna.tf32.f32 %0, %1;" : "=r"(u) : "f"(f)); return u;
}
__device__ __forceinline__ float tf32rf(float f){ return __uint_as_float(tf32r(f)); }

__device__ __forceinline__ void cp_async16(void* s, const void* g){
  unsigned sa = (unsigned)__cvta_generic_to_shared(s);
  asm volatile("cp.async.cg.shared.global [%0], [%1], 16;" :: "r"(sa), "l"(g));
}
__device__ __forceinline__ void cp_commit(){ asm volatile("cp.async.commit_group;"); }
template<int N> __device__ __forceinline__ void cp_wait(){
  asm volatile("cp.async.wait_group %0;" :: "n"(N) : "memory");
}

// tf32 MMA: D(16x8) += A(16x8,row) * B(8x8,col)
__device__ __forceinline__ void mma8(float& d0, float& d1, float& d2, float& d3,
    uint32_t a0, uint32_t a1, uint32_t a2, uint32_t a3, uint32_t b0, uint32_t b1)
{
  asm("mma.sync.aligned.m16n8k8.row.col.f32.tf32.tf32.f32 "
      "{%0,%1,%2,%3},{%4,%5,%6,%7},{%8,%9},{%0,%1,%2,%3};"
      : "+f"(d0), "+f"(d1), "+f"(d2), "+f"(d3)
      : "r"(a0), "r"(a1), "r"(a2), "r"(a3), "r"(b0), "r"(b1));
}

// Load Q A-fragments for 2 k-steps (head_dim 16). rA,rB pre-clamped row indices.
__device__ __forceinline__ void loadQ(const float* Qb, int rA, int rB, int tig,
                                      uint32_t a[2][4])
{
  #pragma unroll
  for (int ks = 0; ks < 2; ks++){
    a[ks][0] = __float_as_uint(Qb[(size_t)rA*KD_ + tig     + 8*ks]);
    a[ks][1] = __float_as_uint(Qb[(size_t)rB*KD_ + tig     + 8*ks]);
    a[ks][2] = __float_as_uint(Qb[(size_t)rA*KD_ + tig + 4 + 8*ks]);
    a[ks][3] = __float_as_uint(Qb[(size_t)rB*KD_ + tig + 4 + 8*ks]);
  }
}

// One 8-key step: scores (2 MMA) -> exp -> (mask) -> P-frag shuffle ->
// ones-MMA row-sum (ls[0]=row g sum, ls[2]=row g+8 sum; fully reduced) ->
// P@V (2 MMA).
template<int MASK>
__device__ __forceinline__ void attn_step(
    const float* __restrict__ Ks, const float* __restrict__ Vs,
    const uint32_t (&aQ)[2][4], float (&o)[2][4], float (&ls)[4],
    int n8, int g, int tig, int lane, int nvalid)
{
  float c0 = 0.f, c1 = 0.f, c2 = 0.f, c3 = 0.f;
  const float* kp = Ks + (n8 + g)*KSTR + tig;
  {
    uint32_t b0 = __float_as_uint(kp[0]),  b1 = __float_as_uint(kp[4]);
    mma8(c0,c1,c2,c3, aQ[0][0],aQ[0][1],aQ[0][2],aQ[0][3], b0, b1);
    uint32_t b2 = __float_as_uint(kp[8]),  b3 = __float_as_uint(kp[12]);
    mma8(c0,c1,c2,c3, aQ[1][0],aQ[1][1],aQ[1][2],aQ[1][3], b2, b3);
  }
  float p0 = ex2f(c0), p1 = ex2f(c1), p2 = ex2f(c2), p3 = ex2f(c3);
  if (MASK){
    int col = n8 + tig*2;
    if (col     >= nvalid){ p0 = 0.f; p2 = 0.f; }
    if (col + 1 >= nvalid){ p1 = 0.f; p3 = 0.f; }
  }
  uint32_t u0 = tf32r(p0), u1 = tf32r(p1), u2 = tf32r(p2), u3 = tf32r(p3);
  // Rearrange D-frag (cols 2t,2t+1) into A-frag (cols t, t+4).
  int src  = (lane & 28) | (tig >> 1);
  int src2 = src + 2;
  uint32_t ev0 = __shfl_sync(0xffffffffu, u0, src ), od0 = __shfl_sync(0xffffffffu, u1, src );
  uint32_t ev1 = __shfl_sync(0xffffffffu, u2, src ), od1 = __shfl_sync(0xffffffffu, u3, src );
  uint32_t ev2 = __shfl_sync(0xffffffffu, u0, src2), od2 = __shfl_sync(0xffffffffu, u1, src2);
  uint32_t ev3 = __shfl_sync(0xffffffffu, u2, src2), od3 = __shfl_sync(0xffffffffu, u3, src2);
  bool odd = (tig & 1);
  uint32_t pa0 = odd ? od0 : ev0;
  uint32_t pa1 = odd ? od1 : ev1;
  uint32_t pa2 = odd ? od2 : ev2;
  uint32_t pa3 = odd ? od3 : ev3;
  const uint32_t one = 0x3f800000u;          // 1.0f (tf32-exact)
  mma8(ls[0], ls[1], ls[2], ls[3], pa0, pa1, pa2, pa3, one, one);
  #pragma unroll
  for (int nt = 0; nt < 2; nt++){
    uint32_t vb0 = __float_as_uint(Vs[(n8 + tig    )*VSTR + nt*8 + g]);
    uint32_t vb1 = __float_as_uint(Vs[(n8 + tig + 4)*VSTR + nt*8 + g]);
    mma8(o[nt][0], o[nt][1], o[nt][2], o[nt][3], pa0, pa1, pa2, pa3, vb0, vb1);
  }
}

// Cooperative chunk staging: 128 keys x 16 floats of K and V (256 threads).
__device__ __forceinline__ void stage_chunk(float* sKb, float* sVb,
    const float* __restrict__ Kg, const float* __restrict__ Vg, int kbase, int tid)
{
  #pragma unroll
  for (int i = 0; i < 2; i++){
    int f4  = tid + i*256;
    int row = f4 >> 2, qq = f4 & 3;
    int gr  = kbase + row;
    if (gr < NT_){
      cp_async16(sKb + row*KSTR + qq*4, Kg + (size_t)gr*KD_ + qq*4);
      cp_async16(sVb + row*VSTR + qq*4, Vg + (size_t)gr*KD_ + qq*4);
    }
  }
}

// ====================== Kernel 1: all projections ==========================
// blockIdx.x < 16 : token tile of 64 rows. Register-tiled fp32 f32x2 GEMM
//                   X[64,128] @ Wcat[128,128] per projection. Exact fp32 fma
//                   (tf32 proj FAILS rel-err: R7). Wcat stored grouped so
//                   B-operand LDS.128 reads are 16-lane CONTIGUOUS
//                   (conflict-free; old cg*8 layout was 2-way conflicted and
//                   pegged L1 at 73%).
// blockIdx.x == 16: station projections (21 rows, scalar).
__global__ __launch_bounds__(256, 2) void k_proj(
    const float* __restrict__ q, const float* __restrict__ h,
    const float* __restrict__ Wqtt, const float* __restrict__ Wqts,
    const float* __restrict__ Wk, const float* __restrict__ Wv,
    const float* __restrict__ Wqst, const float* __restrict__ Wks,
    const float* __restrict__ Wvs)
{
  extern __shared__ float sm[];
  int b  = blockIdx.y;
  int tid = threadIdx.x;

  if (blockIdx.x == 16){
    float* sxq = sm;                 // 21*128
    float* sxh = sm + NS_*D_;
    float* sw  = sm + 2*NS_*D_;      // 128*16
    for (int idx = tid; idx < NS_*D_/4; idx += 256){
      int row = idx >> 5, d4 = idx & 31;
      size_t goff = ((size_t)(b*NN_ + row))*D_ + d4*4;
      ((float4*)sxq)[idx] = *(const float4*)(q + goff);
      ((float4*)sxh)[idx] = *(const float4*)(h + goff);
    }
    const float* Wp[3] = {Wqst, Wks, Wvs};
    for (int p = 0; p < 3; p++){
      const float* src = (p == 0) ? sxq : sxh;
      float scale = (p == 0) ? QSCALE : 1.0f;
      float* Dst = (p == 0) ? g_Qst : (p == 1 ? g_Ks : g_Vs);
      for (int hh = 0; hh < NH_; hh++){
        __syncthreads();
        const float* wp = Wp[p] + hh*D_*KD_;
        for (int idx = tid; idx < D_*KD_; idx += 256) sw[idx] = wp[idx]*scale;
        __syncthreads();
        for (int o = tid; o < NS_*KD_; o += 256){
          int s = o >> 4, k = o & 15;
          float a = 0.f;
          #pragma unroll 8
          for (int d = 0; d < D_; d++) a += src[s*D_ + d] * sw[d*KD_ + k];
          Dst[((size_t)(hh*B_ + b)*NS_ + s)*KD_ + k] = tf32rf(a);
        }
      }
    }
    return;
  }

  // ---------------- token projections: register-tiled GEMM ----------------
  float* sx = sm;                    // 64*XSTR   (x rows: q then h)
  float* sw = sm + 64*XSTR;          // 128*BSTR  (Wcat, grouped layout:
                                     //  sw[k*BSTR + part*64 + grp*4 + j] =
                                     //  W[k][grp*8 + part*4 + j])

  int r0 = blockIdx.x * 64;
  int rg = tid >> 4, cg = tid & 15;            // 4-row group, 8-col group
  int hh = cg >> 1, khalf = (cg & 1)*8;

  const float* Xs[2] = {q, h};
  const float* Wp[4] = {Wqtt, Wqts, Wk, Wv};
  float* Dp[4]; Dp[0]=g_Qtt; Dp[1]=g_Qts; Dp[2]=g_Kc; Dp[3]=g_Vc;

  for (int ph = 0; ph < 2; ph++){
    const float* xs = Xs[ph];
    #pragma unroll
    for (int i = 0; i < 8; i++){
      int idx = tid + i*256;
      int row = idx >> 5, d4 = idx & 31;
      int t = r0 + row; if (t > NT_-1) t = NT_-1;
      ((float4*)(sx + row*XSTR))[d4] =
          *(const float4*)(xs + ((size_t)(b*NN_ + NS_ + t))*D_ + d4*4);
    }
    for (int pp = 0; pp < 2; pp++){
      int p = ph*2 + pp;
      float scale = (p < 2) ? QSCALE : 1.0f;
      const float* wg = Wp[p];
      // stage Wcat in grouped layout (float4 loads, conflict-free STS:
      // dest stride per-lane is d*BSTR, BSTR=132 -> banks 4d, no collision)
      #pragma unroll
      for (int i = 0; i < 16; i++){
        int idx = tid + i*256;              // 4096 float4
        int d = idx & 127, hk = idx >> 7;
        int whh = hk >> 2, k4 = hk & 3;
        float4 v = *(const float4*)(wg + whh*(D_*KD_) + d*KD_ + k4*4);
        v.x *= scale; v.y *= scale; v.z *= scale; v.w *= scale;
        *(float4*)(sw + d*BSTR + (k4 & 1)*64 + (whh*2 + (k4 >> 1))*4) = v;
      }
      __syncthreads();

      ull acc[4][4];
      #pragma unroll
      for (int i = 0; i < 4; i++)
        #pragma unroll
        for (int j = 0; j < 4; j++) acc[i][j] = 0ull;

      const float* Ab = sx + rg*4*XSTR;
      const float* Bb = sw + cg*4;             // lane-contiguous 16B slots
      #pragma unroll 2
      for (int kg = 0; kg < 32; kg++){
        // batch ALL loads for this k-group up front (pipelines across unroll)
        float4 a[4];
        #pragma unroll
        for (int i = 0; i < 4; i++)
          a[i] = *(const float4*)(Ab + i*XSTR + kg*4);
        ulonglong2 b0[4], b1[4];
        #pragma unroll
        for (int kk = 0; kk < 4; kk++){
          b0[kk] = *(const ulonglong2*)(Bb + (kg*4 + kk)*BSTR);        // cols cg*8..+3
          b1[kk] = *(const ulonglong2*)(Bb + (kg*4 + kk)*BSTR + 64);   // cols cg*8+4..+7
        }
        #pragma unroll
        for (int kk = 0; kk < 4; kk++){
          #pragma unroll
          for (int i = 0; i < 4; i++){
            float av = (&a[i].x)[kk];
            ull ap = pack2(av, av);
            acc[i][0] = ffma2(ap, b0[kk].x, acc[i][0]);
            acc[i][1] = ffma2(ap, b0[kk].y, acc[i][1]);
            acc[i][2] = ffma2(ap, b1[kk].x, acc[i][2]);
            acc[i][3] = ffma2(ap, b1[kk].y, acc[i][3]);
          }
        }
      }

      float* dst = Dp[p] + ((size_t)(hh*B_ + b))*NT_*KD_ + khalf;
      #pragma unroll
      for (int i = 0; i < 4; i++){
        int t = r0 + rg*4 + i;
        if (t < NT_){
          float f0,f1,f2,f3,f4,f5,f6,f7;
          unpack2(acc[i][0], f0, f1);
          unpack2(acc[i][1], f2, f3);
          unpack2(acc[i][2], f4, f5);
          unpack2(acc[i][3], f6, f7);
          float4 v0 = make_float4(tf32rf(f0), tf32rf(f1), tf32rf(f2), tf32rf(f3));
          float4 v1 = make_float4(tf32rf(f4), tf32rf(f5), tf32rf(f6), tf32rf(f7));
          *(float4*)(dst + (size_t)t*KD_)     = v0;
          *(float4*)(dst + (size_t)t*KD_ + 4) = v1;
        }
      }
      __syncthreads();
    }
  }
}

// ====================== Kernel 2: all attention ============================
// blockIdx.x < 8 : token-query path (128-query tile, warp = 16 q x all keys).
// blockIdx.x == 8: station-query path (warp = 16 q-rows x key stripe).
// No online max (QSCALE folds NORM*log2e; scores bounded, raw ex2 safe).
// Row sums fall out of the ones-MMA D-fragments already fully reduced.
__global__ __launch_bounds__(256) void k_attn()
{
  extern __shared__ float dsm[];
  float* sK0 = dsm;                                   // [2][128*KSTR]
  float* sV0 = dsm + 2*CHUNK*KSTR;                    // [2][128*VSTR]
  float* sKs = dsm + 2*CHUNK*KSTR + 2*CHUNK*VSTR;     // token: [24*KSTR]
  float* sVs = sKs + 24*KSTR;                         // token: [24*VSTR]
  float* red = dsm + 2*CHUNK*KSTR + 2*CHUNK*VSTR;     // station: [8*32*10]

  int b = blockIdx.y, hh = blockIdx.z;
  int tid = threadIdx.x;
  int w = tid >> 5, lane = tid & 31;
  int g = lane >> 2, tig = lane & 3;
  size_t hb = (size_t)(hh*B_ + b);
  const float* Kg = g_Kc + hb*NT_*KD_;
  const float* Vg = g_Vc + hb*NT_*KD_;
  const int nch = (NT_ + CHUNK - 1)/CHUNK;   // 8

  if (blockIdx.x < 8){
    // ======== token-query path ========
    int qrow = blockIdx.x * 128 + w*16;
    int rA = min(qrow + g,     NT_-1);
    int rB = min(qrow + g + 8, NT_-1);

    // zero station pad rows (21..23) so pad scores are finite then masked
    for (int i = tid; i < 3*KSTR; i += 256) sKs[21*KSTR + i] = 0.f;
    for (int i = tid; i < 3*VSTR; i += 256) sVs[21*VSTR + i] = 0.f;
    // group 1: station K/V
    if (tid < 96){
      int row = tid >> 2, qq = tid & 3;
      if (row < NS_){
        cp_async16(sKs + row*KSTR + qq*4, g_Ks + (hb*NS_ + row)*KD_ + qq*4);
        cp_async16(sVs + row*VSTR + qq*4, g_Vs + (hb*NS_ + row)*KD_ + qq*4);
      }
    }
    cp_commit();
    // group 2: token chunk 0
    stage_chunk(sK0, sV0, Kg, Vg, 0, tid);
    cp_commit();

    uint32_t aT[2][4];
    loadQ(g_Qtt + hb*NT_*KD_, rA, rB, tig, aT);

    // ---- station prologue: full mini-softmax, normalized into os ----
    float os[2][4] = {{0,0,0,0},{0,0,0,0}};
    {
      uint32_t aS[2][4];
      loadQ(g_Qts + hb*NT_*KD_, rA, rB, tig, aS);
      cp_wait<1>();          // group 1 (station) done
      __syncthreads();
      float lsS[4] = {0,0,0,0};
      attn_step<0>(sKs, sVs, aS, os, lsS, 0,  g, tig, lane, 0);
      attn_step<0>(sKs, sVs, aS, os, lsS, 8,  g, tig, lane, 0);
      attn_step<1>(sKs, sVs, aS, os, lsS, 16, g, tig, lane, NS_);
      float isa = 1.f/lsS[0], isb = 1.f/lsS[2];
      #pragma unroll
      for (int nt = 0; nt < 2; nt++){
        os[nt][0] *= isa; os[nt][1] *= isa;
        os[nt][2] *= isb; os[nt][3] *= isb;
      }
    }

    // ---- token mainloop ----
    float ot[2][4] = {{0,0,0,0},{0,0,0,0}};
    float ls[4] = {0,0,0,0};
    for (int c = 0; c < nch; c++){
      if (c + 1 < nch){
        int nb = (c+1) & 1;
        stage_chunk(sK0 + nb*CHUNK*KSTR, sV0 + nb*CHUNK*VSTR, Kg, Vg, (c+1)*CHUNK, tid);
        cp_commit();
        cp_wait<1>();
      } else {
        cp_wait<0>();
      }
      __syncthreads();
      const float* Ks = sK0 + (c&1)*CHUNK*KSTR;
      const float* Vs = sV0 + (c&1)*CHUNK*VSTR;
      int nv = min(CHUNK, NT_ - c*CHUNK);
      int nf = nv >> 3;
      #pragma unroll 4
      for (int n = 0; n < nf; n++)
        attn_step<0>(Ks, Vs, aT, ot, ls, n*8, g, tig, lane, 0);
      if (nv & 7)
        attn_step<1>(Ks, Vs, aT, ot, ls, nf*8, g, tig, lane, nv);
      __syncthreads();
    }

    float ita = 1.f/ls[0], itb = 1.f/ls[2];   // ones-MMA: already full row sums
    int row0 = qrow + g, row1 = qrow + g + 8;
    #pragma unroll
    for (int nt = 0; nt < 2; nt++){
      if (row0 < NT_){
        float2 v; v.x = ot[nt][0]*ita + os[nt][0];
                  v.y = ot[nt][1]*ita + os[nt][1];
        *(float2*)(g_heads + ((size_t)(b*NN_ + NS_ + row0)*NH_ + hh)*KD_ + nt*8 + 2*tig) = v;
      }
      if (row1 < NT_){
        float2 v; v.x = ot[nt][2]*itb + os[nt][2];
                  v.y = ot[nt][3]*itb + os[nt][3];
        *(float2*)(g_heads + ((size_t)(b*NN_ + NS_ + row1)*NH_ + hh)*KD_ + nt*8 + 2*tig) = v;
      }
    }
  } else {
    // ======== station-query path ========
    int rt = w & 1, s = w >> 1;        // 2 q-row-tiles x 4 key stripes
    int rA = min(rt*16 + g,     NS_-1);
    int rB = min(rt*16 + g + 8, NS_-1);
    uint32_t aQ[2][4];
    loadQ(g_Qst + hb*NS_*KD_, rA, rB, tig, aQ);

    float o[2][4] = {{0,0,0,0},{0,0,0,0}};
    float ls[4] = {0,0,0,0};

    stage_chunk(sK0, sV0, Kg, Vg, 0, tid);
    cp_commit();
    for (int c = 0; c < nch; c++){
      if (c + 1 < nch){
        int nb = (c+1) & 1;
        stage_chunk(sK0 + nb*CHUNK*KSTR, sV0 + nb*CHUNK*VSTR, Kg, Vg, (c+1)*CHUNK, tid);
        cp_commit();
        cp_wait<1>();
      } else {
        cp_wait<0>();
      }
      __syncthreads();
      const float* Ks = sK0 + (c&1)*CHUNK*KSTR;
      const float* Vs = sV0 + (c&1)*CHUNK*VSTR;
      int nv = min(CHUNK, NT_ - c*CHUNK);
      #pragma unroll
      for (int j = 0; j < 4; j++){
        int n8 = (s*4 + j)*8;
        if (n8 + 8 <= nv)
          attn_step<0>(Ks, Vs, aQ, o, ls, n8, g, tig, lane, 0);
        else if (n8 < nv)
          attn_step<1>(Ks, Vs, aQ, o, ls, n8, g, tig, lane, nv);
      }
      __syncthreads();
    }

    float* rp = red + (w*32 + lane)*10;
    rp[0]=o[0][0]; rp[1]=o[0][1]; rp[2]=o[0][2]; rp[3]=o[0][3];
    rp[4]=o[1][0]; rp[5]=o[1][1]; rp[6]=o[1][2]; rp[7]=o[1][3];
    rp[8]=ls[0]; rp[9]=ls[2];
    __syncthreads();
    if (w < 2){
      float la = ls[0], lb = ls[2];
      #pragma unroll
      for (int ss = 1; ss < 4; ss++){
        float* qp = red + ((w + 2*ss)*32 + lane)*10;
        o[0][0]+=qp[0]; o[0][1]+=qp[1]; o[0][2]+=qp[2]; o[0][3]+=qp[3];
        o[1][0]+=qp[4]; o[1][1]+=qp[5]; o[1][2]+=qp[6]; o[1][3]+=qp[7];
        la += qp[8]; lb += qp[9];
      }
      float ia = 1.f/la, ib = 1.f/lb;
      int r0 = rt*16 + g, r1 = r0 + 8;
      #pragma unroll
      for (int nt = 0; nt < 2; nt++){
        if (r0 < NS_){
          float2 v; v.x = o[nt][0]*ia; v.y = o[nt][1]*ia;
          *(float2*)(g_heads + ((size_t)(b*NN_ + r0)*NH_ + hh)*KD_ + nt*8 + 2*tig) = v;
        }
        if (r1 < NS_){
          float2 v; v.x = o[nt][2]*ib; v.y = o[nt][3]*ib;
          *(float2*)(g_heads + ((size_t)(b*NN_ + r1)*NH_ + hh)*KD_ + nt*8 + 2*tig) = v;
        }
      }
    }
  }
}

// ================ Kernel 3: output GEMM (fp32 f32x2, value path) ===========
__global__ __launch_bounds__(256, 2) void k_out(
    const float* __restrict__ Wout, float* __restrict__ out)
{
  extern __shared__ float sm[];
  float* sA  = sm;              // 64*128
  float* sWt = sm + 64*D_;      // 128*132 transposed
  int m0 = blockIdx.x * 64;
  int tid = threadIdx.x;
  for (int idx = tid; idx < 64*32; idx += 256){
    int r = idx >> 5, d4 = idx & 31;
    ((float4*)(sA + r*D_))[d4] = ((const float4*)(g_heads + (size_t)(m0 + r)*D_))[d4];
  }
  for (int idx = tid; idx < D_*D_; idx += 256){
    int c = idx >> 7, e = idx & 127;
    sWt[e*132 + c] = Wout[idx];
  }
  __syncthreads();
  int rg = tid >> 4, cg = tid & 15;
  ull acc2[4][8];
  #pragma unroll
  for (int i = 0; i < 4; i++)
    #pragma unroll
    for (int e = 0; e < 8; e++) acc2[i][e] = 0ull;
  #pragma unroll 2
  for (int d4 = 0; d4 < 32; d4++){
    ulonglong2 a[4];
    #pragma unroll
    for (int i = 0; i < 4; i++)
      a[i] = *(const ulonglong2*)(sA + (rg*4 + i)*D_ + d4*4);
    #pragma unroll
    for (int e = 0; e < 8; e++){
      ulonglong2 wv = *(const ulonglong2*)(sWt + (cg*8 + e)*132 + d4*4);
      #pragma unroll
      for (int i = 0; i < 4; i++){
        acc2[i][e] = ffma2(a[i].x, wv.x, acc2[i][e]);
        acc2[i][e] = ffma2(a[i].y, wv.y, acc2[i][e]);
      }
    }
  }
  #pragma unroll
  for (int i = 0; i < 4; i++){
    #pragma unroll
    for (int e = 0; e < 8; e++){
      float lo, hi; unpack2(acc2[i][e], lo, hi);
      out[(size_t)(m0 + rg*4 + i)*D_ + cg*8 + e] = lo + hi;
    }
  }
}

// ===========================================================================
extern "C" void kernel_launch(void* const* d_in, const int* in_sizes, int n_in,
                              void* d_out, int out_size)
{
  const float* q     = (const float*)d_in[0];
  const float* h     = (const float*)d_in[1];
  const float* Wq_ts = (const float*)d_in[2];   // W_query_custom    -> Q_ts
  const float* Wq_tt = (const float*)d_in[3];   // W_query_custom_1  -> Q_tt
  const float* Wk_c  = (const float*)d_in[4];   // W_key_custom
  const float* Wv_c  = (const float*)d_in[5];   // W_val_custom
  const float* Wq_st = (const float*)d_in[6];   // W_query_charge_1  -> Q_st
  const float* Wk_s  = (const float*)d_in[7];   // W_key_charge
  const float* Wv_s  = (const float*)d_in[8];   // W_val_charge
  const float* Wout  = (const float*)d_in[9];
  float* out = (float*)d_out;

  int smem1 = (64*XSTR + 128*BSTR)*(int)sizeof(float);   // 101376 B
  cudaFuncSetAttribute(k_proj, cudaFuncAttributeMaxDynamicSharedMemorySize, smem1);
  int smemA = (2*CHUNK*KSTR + 2*CHUNK*VSTR + 8*32*10)*(int)sizeof(float);
  cudaFuncSetAttribute(k_attn, cudaFuncAttributeMaxDynamicSharedMemorySize, smemA);
  int smem5 = (64*D_ + D_*132)*(int)sizeof(float);
  cudaFuncSetAttribute(k_out, cudaFuncAttributeMaxDynamicSharedMemorySize, smem5);

  k_proj<<<dim3(17, 32), 256, smem1>>>(q, h, Wq_tt, Wq_ts, Wk_c, Wv_c,
                                       Wq_st, Wk_s, Wv_s);
  k_attn<<<dim3(9, 32, 8), 256, smemA>>>();
  k_out<<<512, 256, smem5>>>(Wout, out);
}

// round 15
// speedup vs baseline: 1.0952x; 1.0348x over previous
#include <cuda_runtime.h>
#include <cstdint>

typedef unsigned long long ull;

#define B_   32
#define NH_  8
#define NN_  1024
#define NS_  21
#define NT_  1003
#define D_   128
#define KD_  16
#define HB_  (NH_*B_)

// NORM * log2(e) folded into query projections so softmax uses raw ex2.
#define QSCALE 0.36067376022224085f

#define CHUNK 128
#define KSTR  20    // K smem row stride (floats): conflict-free score-frag loads
#define VSTR  24    // V smem row stride (floats): conflict-free PV-frag loads
#define XSTR  132   // x smem row stride in proj
#define BSTR  132   // Wcat smem row stride in proj

// ---------------- scratch (device globals; no allocation allowed) ----------
__device__ float g_Qtt[HB_*NT_*KD_];
__device__ float g_Qts[HB_*NT_*KD_];
__device__ float g_Kc [HB_*NT_*KD_];
__device__ float g_Vc [HB_*NT_*KD_];
__device__ float g_Qst[HB_*NS_*KD_];
__device__ float g_Ks [HB_*NS_*KD_];
__device__ float g_Vs [HB_*NS_*KD_];
__device__ float g_heads[B_*NN_*NH_*KD_];   // layout [b][n][h][k]

// ---------------- helpers ---------------------------------------------------
__device__ __forceinline__ ull pack2(float lo, float hi){
  ull r; asm("mov.b64 %0, {%1,%2};" : "=l"(r) : "f"(lo), "f"(hi)); return r;
}
__device__ __forceinline__ void unpack2(ull v, float& lo, float& hi){
  asm("mov.b64 {%0,%1}, %2;" : "=f"(lo), "=f"(hi) : "l"(v));
}
__device__ __forceinline__ ull ffma2(ull a, ull b, ull c){
  ull d; asm("fma.rn.f32x2 %0, %1, %2, %3;" : "=l"(d) : "l"(a), "l"(b), "l"(c)); return d;
}
__device__ __forceinline__ float ex2f(float x){
  float r; asm("ex2.approx.f32 %0, %1;" : "=f"(r) : "f"(x)); return r;
}
__device__ __forceinline__ uint32_t tf32r(float f){
  uint32_t u; asm("cvt.rna.tf32.f32 %0, %1;" : "=r"(u) : "f"(f)); return u;
}
__device__ __forceinline__ float tf32rf(float f){ return __uint_as_float(tf32r(f)); }

__device__ __forceinline__ void cp_async16(void* s, const void* g){
  unsigned sa = (unsigned)__cvta_generic_to_shared(s);
  asm volatile("cp.async.cg.shared.global [%0], [%1], 16;" :: "r"(sa), "l"(g));
}
__device__ __forceinline__ void cp_commit(){ asm volatile("cp.async.commit_group;"); }
template<int N> __device__ __forceinline__ void cp_wait(){
  asm volatile("cp.async.wait_group %0;" :: "n"(N) : "memory");
}

// tf32 MMA: D(16x8) += A(16x8,row) * B(8x8,col)
__device__ __forceinline__ void mma8(float& d0, float& d1, float& d2, float& d3,
    uint32_t a0, uint32_t a1, uint32_t a2, uint32_t a3, uint32_t b0, uint32_t b1)
{
  asm("mma.sync.aligned.m16n8k8.row.col.f32.tf32.tf32.f32 "
      "{%0,%1,%2,%3},{%4,%5,%6,%7},{%8,%9},{%0,%1,%2,%3};"
      : "+f"(d0), "+f"(d1), "+f"(d2), "+f"(d3)
      : "r"(a0), "r"(a1), "r"(a2), "r"(a3), "r"(b0), "r"(b1));
}

// Load Q A-fragments for 2 k-steps (head_dim 16). rA,rB pre-clamped row indices.
__device__ __forceinline__ void loadQ(const float* Qb, int rA, int rB, int tig,
                                      uint32_t a[2][4])
{
  #pragma unroll
  for (int ks = 0; ks < 2; ks++){
    a[ks][0] = __float_as_uint(Qb[(size_t)rA*KD_ + tig     + 8*ks]);
    a[ks][1] = __float_as_uint(Qb[(size_t)rB*KD_ + tig     + 8*ks]);
    a[ks][2] = __float_as_uint(Qb[(size_t)rA*KD_ + tig + 4 + 8*ks]);
    a[ks][3] = __float_as_uint(Qb[(size_t)rB*KD_ + tig + 4 + 8*ks]);
  }
}

// One 8-key step: scores (2 MMA) -> exp -> (mask) -> P-frag shuffle ->
// ones-MMA row-sum (ls[0]=row g sum, ls[2]=row g+8 sum; fully reduced) ->
// P@V (2 MMA).
template<int MASK>
__device__ __forceinline__ void attn_step(
    const float* __restrict__ Ks, const float* __restrict__ Vs,
    const uint32_t (&aQ)[2][4], float (&o)[2][4], float (&ls)[4],
    int n8, int g, int tig, int lane, int nvalid)
{
  float c0 = 0.f, c1 = 0.f, c2 = 0.f, c3 = 0.f;
  const float* kp = Ks + (n8 + g)*KSTR + tig;
  {
    uint32_t b0 = __float_as_uint(kp[0]),  b1 = __float_as_uint(kp[4]);
    mma8(c0,c1,c2,c3, aQ[0][0],aQ[0][1],aQ[0][2],aQ[0][3], b0, b1);
    uint32_t b2 = __float_as_uint(kp[8]),  b3 = __float_as_uint(kp[12]);
    mma8(c0,c1,c2,c3, aQ[1][0],aQ[1][1],aQ[1][2],aQ[1][3], b2, b3);
  }
  float p0 = ex2f(c0), p1 = ex2f(c1), p2 = ex2f(c2), p3 = ex2f(c3);
  if (MASK){
    int col = n8 + tig*2;
    if (col     >= nvalid){ p0 = 0.f; p2 = 0.f; }
    if (col + 1 >= nvalid){ p1 = 0.f; p3 = 0.f; }
  }
  uint32_t u0 = tf32r(p0), u1 = tf32r(p1), u2 = tf32r(p2), u3 = tf32r(p3);
  // Rearrange D-frag (cols 2t,2t+1) into A-frag (cols t, t+4).
  int src  = (lane & 28) | (tig >> 1);
  int src2 = src + 2;
  uint32_t ev0 = __shfl_sync(0xffffffffu, u0, src ), od0 = __shfl_sync(0xffffffffu, u1, src );
  uint32_t ev1 = __shfl_sync(0xffffffffu, u2, src ), od1 = __shfl_sync(0xffffffffu, u3, src );
  uint32_t ev2 = __shfl_sync(0xffffffffu, u0, src2), od2 = __shfl_sync(0xffffffffu, u1, src2);
  uint32_t ev3 = __shfl_sync(0xffffffffu, u2, src2), od3 = __shfl_sync(0xffffffffu, u3, src2);
  bool odd = (tig & 1);
  uint32_t pa0 = odd ? od0 : ev0;
  uint32_t pa1 = odd ? od1 : ev1;
  uint32_t pa2 = odd ? od2 : ev2;
  uint32_t pa3 = odd ? od3 : ev3;
  const uint32_t one = 0x3f800000u;          // 1.0f (tf32-exact)
  mma8(ls[0], ls[1], ls[2], ls[3], pa0, pa1, pa2, pa3, one, one);
  #pragma unroll
  for (int nt = 0; nt < 2; nt++){
    uint32_t vb0 = __float_as_uint(Vs[(n8 + tig    )*VSTR + nt*8 + g]);
    uint32_t vb1 = __float_as_uint(Vs[(n8 + tig + 4)*VSTR + nt*8 + g]);
    mma8(o[nt][0], o[nt][1], o[nt][2], o[nt][3], pa0, pa1, pa2, pa3, vb0, vb1);
  }
}

// Cooperative chunk staging: 128 keys x 16 floats of K and V (256 threads).
__device__ __forceinline__ void stage_chunk(float* sKb, float* sVb,
    const float* __restrict__ Kg, const float* __restrict__ Vg, int kbase, int tid)
{
  #pragma unroll
  for (int i = 0; i < 2; i++){
    int f4  = tid + i*256;
    int row = f4 >> 2, qq = f4 & 3;
    int gr  = kbase + row;
    if (gr < NT_){
      cp_async16(sKb + row*KSTR + qq*4, Kg + (size_t)gr*KD_ + qq*4);
      cp_async16(sVb + row*VSTR + qq*4, Vg + (size_t)gr*KD_ + qq*4);
    }
  }
}

// ====================== Kernel 1: all projections ==========================
// blockIdx.x < 16 : token tile of 64 rows. Register-tiled fp32 f32x2 GEMM
//                   X[64,128] @ Wcat[128,128] per projection. W staged in two
//                   64-k halves -> smem 67.6KB -> 3 blocks/SM (was 2; kernel
//                   measured occupancy-latency-bound at occ 22%).
//                   Exact fp32 fma (tf32 proj FAILS rel-err: R7).
// blockIdx.x == 16: station projections (21 rows, scalar).
__global__ __launch_bounds__(256, 3) void k_proj(
    const float* __restrict__ q, const float* __restrict__ h,
    const float* __restrict__ Wqtt, const float* __restrict__ Wqts,
    const float* __restrict__ Wk, const float* __restrict__ Wv,
    const float* __restrict__ Wqst, const float* __restrict__ Wks,
    const float* __restrict__ Wvs)
{
  extern __shared__ float sm[];
  int b  = blockIdx.y;
  int tid = threadIdx.x;

  if (blockIdx.x == 16){
    float* sxq = sm;                 // 21*128
    float* sxh = sm + NS_*D_;
    float* sw  = sm + 2*NS_*D_;      // 128*16
    for (int idx = tid; idx < NS_*D_/4; idx += 256){
      int row = idx >> 5, d4 = idx & 31;
      size_t goff = ((size_t)(b*NN_ + row))*D_ + d4*4;
      ((float4*)sxq)[idx] = *(const float4*)(q + goff);
      ((float4*)sxh)[idx] = *(const float4*)(h + goff);
    }
    const float* Wp[3] = {Wqst, Wks, Wvs};
    for (int p = 0; p < 3; p++){
      const float* src = (p == 0) ? sxq : sxh;
      float scale = (p == 0) ? QSCALE : 1.0f;
      float* Dst = (p == 0) ? g_Qst : (p == 1 ? g_Ks : g_Vs);
      for (int hh = 0; hh < NH_; hh++){
        __syncthreads();
        const float* wp = Wp[p] + hh*D_*KD_;
        for (int idx = tid; idx < D_*KD_; idx += 256) sw[idx] = wp[idx]*scale;
        __syncthreads();
        for (int o = tid; o < NS_*KD_; o += 256){
          int s = o >> 4, k = o & 15;
          float a = 0.f;
          #pragma unroll 8
          for (int d = 0; d < D_; d++) a += src[s*D_ + d] * sw[d*KD_ + k];
          Dst[((size_t)(hh*B_ + b)*NS_ + s)*KD_ + k] = tf32rf(a);
        }
      }
    }
    return;
  }

  // ---------------- token projections: register-tiled GEMM ----------------
  float* sx = sm;                    // 64*XSTR   (x rows: q then h)
  float* sw = sm + 64*XSTR;          // 64*BSTR   (half of Wcat k-rows,
                                     //  grouped conflict-free layout)

  int r0 = blockIdx.x * 64;
  int rg = tid >> 4, cg = tid & 15;            // 4-row group, 8-col group
  int hh = cg >> 1, khalf = (cg & 1)*8;

  const float* Xs[2] = {q, h};
  const float* Wp[4] = {Wqtt, Wqts, Wk, Wv};
  float* Dp[4]; Dp[0]=g_Qtt; Dp[1]=g_Qts; Dp[2]=g_Kc; Dp[3]=g_Vc;

  for (int ph = 0; ph < 2; ph++){
    const float* xs = Xs[ph];
    #pragma unroll
    for (int i = 0; i < 8; i++){
      int idx = tid + i*256;
      int row = idx >> 5, d4 = idx & 31;
      int t = r0 + row; if (t > NT_-1) t = NT_-1;
      ((float4*)(sx + row*XSTR))[d4] =
          *(const float4*)(xs + ((size_t)(b*NN_ + NS_ + t))*D_ + d4*4);
    }
    for (int pp = 0; pp < 2; pp++){
      int p = ph*2 + pp;
      float scale = (p < 2) ? QSCALE : 1.0f;
      const float* wg = Wp[p];

      ull acc[4][4];
      #pragma unroll
      for (int i = 0; i < 4; i++)
        #pragma unroll
        for (int j = 0; j < 4; j++) acc[i][j] = 0ull;

      for (int hf = 0; hf < 2; hf++){
        // stage this 64-k half of Wcat (grouped conflict-free layout)
        #pragma unroll
        for (int i = 0; i < 8; i++){
          int idx = tid + i*256;              // 2048 float4
          int d = idx & 63, hk = idx >> 6;
          int whh = hk >> 2, k4 = hk & 3;
          int dg = hf*64 + d;
          float4 v = *(const float4*)(wg + whh*(D_*KD_) + dg*KD_ + k4*4);
          v.x *= scale; v.y *= scale; v.z *= scale; v.w *= scale;
          *(float4*)(sw + d*BSTR + (k4 & 1)*64 + (whh*2 + (k4 >> 1))*4) = v;
        }
        __syncthreads();   // also covers x load (hf==0, pp==0)

        const float* Ab = sx + rg*4*XSTR + hf*64;
        const float* Bb = sw + cg*4;             // lane-contiguous 16B slots
        #pragma unroll 2
        for (int kg = 0; kg < 16; kg++){
          float4 a[4];
          #pragma unroll
          for (int i = 0; i < 4; i++)
            a[i] = *(const float4*)(Ab + i*XSTR + kg*4);
          #pragma unroll
          for (int kk = 0; kk < 4; kk++){
            ulonglong2 b0 = *(const ulonglong2*)(Bb + (kg*4 + kk)*BSTR);
            ulonglong2 b1 = *(const ulonglong2*)(Bb + (kg*4 + kk)*BSTR + 64);
            #pragma unroll
            for (int i = 0; i < 4; i++){
              float av = (&a[i].x)[kk];
              ull ap = pack2(av, av);
              acc[i][0] = ffma2(ap, b0.x, acc[i][0]);
              acc[i][1] = ffma2(ap, b0.y, acc[i][1]);
              acc[i][2] = ffma2(ap, b1.x, acc[i][2]);
              acc[i][3] = ffma2(ap, b1.y, acc[i][3]);
            }
          }
        }
        __syncthreads();   // before sw is overwritten (next half / next proj)
      }

      float* dst = Dp[p] + ((size_t)(hh*B_ + b))*NT_*KD_ + khalf;
      #pragma unroll
      for (int i = 0; i < 4; i++){
        int t = r0 + rg*4 + i;
        if (t < NT_){
          float f0,f1,f2,f3,f4,f5,f6,f7;
          unpack2(acc[i][0], f0, f1);
          unpack2(acc[i][1], f2, f3);
          unpack2(acc[i][2], f4, f5);
          unpack2(acc[i][3], f6, f7);
          float4 v0 = make_float4(tf32rf(f0), tf32rf(f1), tf32rf(f2), tf32rf(f3));
          float4 v1 = make_float4(tf32rf(f4), tf32rf(f5), tf32rf(f6), tf32rf(f7));
          *(float4*)(dst + (size_t)t*KD_)     = v0;
          *(float4*)(dst + (size_t)t*KD_ + 4) = v1;
        }
      }
    }
  }
}

// ====================== Kernel 2: all attention ============================
// blockIdx.x < 8 : token-query path (128-query tile, warp = 16 q x all keys).
// blockIdx.x == 8: station-query path (warp = 16 q-rows x key stripe).
// No online max (QSCALE folds NORM*log2e; scores bounded, raw ex2 safe).
// Row sums fall out of the ones-MMA D-fragments already fully reduced.
// (256,3): force 3 blocks/SM (smem 55.7KB x3 fits) — 6 warps/SMSP to hide
// the per-step MMA->ex2->shfl->MMA chain (measured IPC ~0.4/warp).
__global__ __launch_bounds__(256, 3) void k_attn()
{
  extern __shared__ float dsm[];
  float* sK0 = dsm;                                   // [2][128*KSTR]
  float* sV0 = dsm + 2*CHUNK*KSTR;                    // [2][128*VSTR]
  float* sKs = dsm + 2*CHUNK*KSTR + 2*CHUNK*VSTR;     // token: [24*KSTR]
  float* sVs = sKs + 24*KSTR;                         // token: [24*VSTR]
  float* red = dsm + 2*CHUNK*KSTR + 2*CHUNK*VSTR;     // station: [8*32*10]

  int b = blockIdx.y, hh = blockIdx.z;
  int tid = threadIdx.x;
  int w = tid >> 5, lane = tid & 31;
  int g = lane >> 2, tig = lane & 3;
  size_t hb = (size_t)(hh*B_ + b);
  const float* Kg = g_Kc + hb*NT_*KD_;
  const float* Vg = g_Vc + hb*NT_*KD_;
  const int nch = (NT_ + CHUNK - 1)/CHUNK;   // 8

  if (blockIdx.x < 8){
    // ======== token-query path ========
    int qrow = blockIdx.x * 128 + w*16;
    int rA = min(qrow + g,     NT_-1);
    int rB = min(qrow + g + 8, NT_-1);

    // zero station pad rows (21..23) so pad scores are finite then masked
    for (int i = tid; i < 3*KSTR; i += 256) sKs[21*KSTR + i] = 0.f;
    for (int i = tid; i < 3*VSTR; i += 256) sVs[21*VSTR + i] = 0.f;
    // group 1: station K/V
    if (tid < 96){
      int row = tid >> 2, qq = tid & 3;
      if (row < NS_){
        cp_async16(sKs + row*KSTR + qq*4, g_Ks + (hb*NS_ + row)*KD_ + qq*4);
        cp_async16(sVs + row*VSTR + qq*4, g_Vs + (hb*NS_ + row)*KD_ + qq*4);
      }
    }
    cp_commit();
    // group 2: token chunk 0
    stage_chunk(sK0, sV0, Kg, Vg, 0, tid);
    cp_commit();

    uint32_t aT[2][4];
    loadQ(g_Qtt + hb*NT_*KD_, rA, rB, tig, aT);

    // ---- station prologue: full mini-softmax, normalized into os ----
    float os[2][4] = {{0,0,0,0},{0,0,0,0}};
    {
      uint32_t aS[2][4];
      loadQ(g_Qts + hb*NT_*KD_, rA, rB, tig, aS);
      cp_wait<1>();          // group 1 (station) done
      __syncthreads();
      float lsS[4] = {0,0,0,0};
      attn_step<0>(sKs, sVs, aS, os, lsS, 0,  g, tig, lane, 0);
      attn_step<0>(sKs, sVs, aS, os, lsS, 8,  g, tig, lane, 0);
      attn_step<1>(sKs, sVs, aS, os, lsS, 16, g, tig, lane, NS_);
      float isa = 1.f/lsS[0], isb = 1.f/lsS[2];
      #pragma unroll
      for (int nt = 0; nt < 2; nt++){
        os[nt][0] *= isa; os[nt][1] *= isa;
        os[nt][2] *= isb; os[nt][3] *= isb;
      }
    }

    // ---- token mainloop ----
    float ot[2][4] = {{0,0,0,0},{0,0,0,0}};
    float ls[4] = {0,0,0,0};
    for (int c = 0; c < nch; c++){
      if (c + 1 < nch){
        int nb = (c+1) & 1;
        stage_chunk(sK0 + nb*CHUNK*KSTR, sV0 + nb*CHUNK*VSTR, Kg, Vg, (c+1)*CHUNK, tid);
        cp_commit();
        cp_wait<1>();
      } else {
        cp_wait<0>();
      }
      __syncthreads();
      const float* Ks = sK0 + (c&1)*CHUNK*KSTR;
      const float* Vs = sV0 + (c&1)*CHUNK*VSTR;
      int nv = min(CHUNK, NT_ - c*CHUNK);
      int nf = nv >> 3;
      #pragma unroll 4
      for (int n = 0; n < nf; n++)
        attn_step<0>(Ks, Vs, aT, ot, ls, n*8, g, tig, lane, 0);
      if (nv & 7)
        attn_step<1>(Ks, Vs, aT, ot, ls, nf*8, g, tig, lane, nv);
      __syncthreads();
    }

    float ita = 1.f/ls[0], itb = 1.f/ls[2];   // ones-MMA: already full row sums
    int row0 = qrow + g, row1 = qrow + g + 8;
    #pragma unroll
    for (int nt = 0; nt < 2; nt++){
      if (row0 < NT_){
        float2 v; v.x = ot[nt][0]*ita + os[nt][0];
                  v.y = ot[nt][1]*ita + os[nt][1];
        *(float2*)(g_heads + ((size_t)(b*NN_ + NS_ + row0)*NH_ + hh)*KD_ + nt*8 + 2*tig) = v;
      }
      if (row1 < NT_){
        float2 v; v.x = ot[nt][2]*itb + os[nt][2];
                  v.y = ot[nt][3]*itb + os[nt][3];
        *(float2*)(g_heads + ((size_t)(b*NN_ + NS_ + row1)*NH_ + hh)*KD_ + nt*8 + 2*tig) = v;
      }
    }
  } else {
    // ======== station-query path ========
    int rt = w & 1, s = w >> 1;        // 2 q-row-tiles x 4 key stripes
    int rA = min(rt*16 + g,     NS_-1);
    int rB = min(rt*16 + g + 8, NS_-1);
    uint32_t aQ[2][4];
    loadQ(g_Qst + hb*NS_*KD_, rA, rB, tig, aQ);

    float o[2][4] = {{0,0,0,0},{0,0,0,0}};
    float ls[4] = {0,0,0,0};

    stage_chunk(sK0, sV0, Kg, Vg, 0, tid);
    cp_commit();
    for (int c = 0; c < nch; c++){
      if (c + 1 < nch){
        int nb = (c+1) & 1;
        stage_chunk(sK0 + nb*CHUNK*KSTR, sV0 + nb*CHUNK*VSTR, Kg, Vg, (c+1)*CHUNK, tid);
        cp_commit();
        cp_wait<1>();
      } else {
        cp_wait<0>();
      }
      __syncthreads();
      const float* Ks = sK0 + (c&1)*CHUNK*KSTR;
      const float* Vs = sV0 + (c&1)*CHUNK*VSTR;
      int nv = min(CHUNK, NT_ - c*CHUNK);
      #pragma unroll
      for (int j = 0; j < 4; j++){
        int n8 = (s*4 + j)*8;
        if (n8 + 8 <= nv)
          attn_step<0>(Ks, Vs, aQ, o, ls, n8, g, tig, lane, 0);
        else if (n8 < nv)
          attn_step<1>(Ks, Vs, aQ, o, ls, n8, g, tig, lane, nv);
      }
      __syncthreads();
    }

    float* rp = red + (w*32 + lane)*10;
    rp[0]=o[0][0]; rp[1]=o[0][1]; rp[2]=o[0][2]; rp[3]=o[0][3];
    rp[4]=o[1][0]; rp[5]=o[1][1]; rp[6]=o[1][2]; rp[7]=o[1][3];
    rp[8]=ls[0]; rp[9]=ls[2];
    __syncthreads();
    if (w < 2){
      float la = ls[0], lb = ls[2];
      #pragma unroll
      for (int ss = 1; ss < 4; ss++){
        float* qp = red + ((w + 2*ss)*32 + lane)*10;
        o[0][0]+=qp[0]; o[0][1]+=qp[1]; o[0][2]+=qp[2]; o[0][3]+=qp[3];
        o[1][0]+=qp[4]; o[1][1]+=qp[5]; o[1][2]+=qp[6]; o[1][3]+=qp[7];
        la += qp[8]; lb += qp[9];
      }
      float ia = 1.f/la, ib = 1.f/lb;
      int r0 = rt*16 + g, r1 = r0 + 8;
      #pragma unroll
      for (int nt = 0; nt < 2; nt++){
        if (r0 < NS_){
          float2 v; v.x = o[nt][0]*ia; v.y = o[nt][1]*ia;
          *(float2*)(g_heads + ((size_t)(b*NN_ + r0)*NH_ + hh)*KD_ + nt*8 + 2*tig) = v;
        }
        if (r1 < NS_){
          float2 v; v.x = o[nt][2]*ib; v.y = o[nt][3]*ib;
          *(float2*)(g_heads + ((size_t)(b*NN_ + r1)*NH_ + hh)*KD_ + nt*8 + 2*tig) = v;
        }
      }
    }
  }
}

// ================ Kernel 3: output GEMM (fp32 f32x2, value path) ===========
__global__ __launch_bounds__(256, 2) void k_out(
    const float* __restrict__ Wout, float* __restrict__ out)
{
  extern __shared__ float sm[];
  float* sA  = sm;              // 64*128
  float* sWt = sm + 64*D_;      // 128*132 transposed
  int m0 = blockIdx.x * 64;
  int tid = threadIdx.x;
  for (int idx = tid; idx < 64*32; idx += 256){
    int r = idx >> 5, d4 = idx & 31;
    ((float4*)(sA + r*D_))[d4] = ((const float4*)(g_heads + (size_t)(m0 + r)*D_))[d4];
  }
  for (int idx = tid; idx < D_*D_; idx += 256){
    int c = idx >> 7, e = idx & 127;
    sWt[e*132 + c] = Wout[idx];
  }
  __syncthreads();
  int rg = tid >> 4, cg = tid & 15;
  ull acc2[4][8];
  #pragma unroll
  for (int i = 0; i < 4; i++)
    #pragma unroll
    for (int e = 0; e < 8; e++) acc2[i][e] = 0ull;
  #pragma unroll 2
  for (int d4 = 0; d4 < 32; d4++){
    ulonglong2 a[4];
    #pragma unroll
    for (int i = 0; i < 4; i++)
      a[i] = *(const ulonglong2*)(sA + (rg*4 + i)*D_ + d4*4);
    #pragma unroll
    for (int e = 0; e < 8; e++){
      ulonglong2 wv = *(const ulonglong2*)(sWt + (cg*8 + e)*132 + d4*4);
      #pragma unroll
      for (int i = 0; i < 4; i++){
        acc2[i][e] = ffma2(a[i].x, wv.x, acc2[i][e]);
        acc2[i][e] = ffma2(a[i].y, wv.y, acc2[i][e]);
      }
    }
  }
  #pragma unroll
  for (int i = 0; i < 4; i++){
    #pragma unroll
    for (int e = 0; e < 8; e++){
      float lo, hi; unpack2(acc2[i][e], lo, hi);
      out[(size_t)(m0 + rg*4 + i)*D_ + cg*8 + e] = lo + hi;
    }
  }
}

// ===========================================================================
extern "C" void kernel_launch(void* const* d_in, const int* in_sizes, int n_in,
                              void* d_out, int out_size)
{
  const float* q     = (const float*)d_in[0];
  const float* h     = (const float*)d_in[1];
  const float* Wq_ts = (const float*)d_in[2];   // W_query_custom    -> Q_ts
  const float* Wq_tt = (const float*)d_in[3];   // W_query_custom_1  -> Q_tt
  const float* Wk_c  = (const float*)d_in[4];   // W_key_custom
  const float* Wv_c  = (const float*)d_in[5];   // W_val_custom
  const float* Wq_st = (const float*)d_in[6];   // W_query_charge_1  -> Q_st
  const float* Wk_s  = (const float*)d_in[7];   // W_key_charge
  const float* Wv_s  = (const float*)d_in[8];   // W_val_charge
  const float* Wout  = (const float*)d_in[9];
  float* out = (float*)d_out;

  int smem1 = (64*XSTR + 64*BSTR)*(int)sizeof(float);   // 67584 B -> 3 blk/SM
  cudaFuncSetAttribute(k_proj, cudaFuncAttributeMaxDynamicSharedMemorySize, smem1);
  int smemA = (2*CHUNK*KSTR + 2*CHUNK*VSTR + 8*32*10)*(int)sizeof(float);
  cudaFuncSetAttribute(k_attn, cudaFuncAttributeMaxDynamicSharedMemorySize, smemA);
  int smem5 = (64*D_ + D_*132)*(int)sizeof(float);
  cudaFuncSetAttribute(k_out, cudaFuncAttributeMaxDynamicSharedMemorySize, smem5);

  k_proj<<<dim3(17, 32), 256, smem1>>>(q, h, Wq_tt, Wq_ts, Wk_c, Wv_c,
                                       Wq_st, Wk_s, Wv_s);
  k_attn<<<dim3(9, 32, 8), 256, smemA>>>();
  k_out<<<512, 256, smem5>>>(Wout, out);
}

// round 16
// speedup vs baseline: 1.1591x; 1.0583x over previous
#include <cuda_runtime.h>
#include <cstdint>

typedef unsigned long long ull;

#define B_   32
#define NH_  8
#define NN_  1024
#define NS_  21
#define NT_  1003
#define D_   128
#define KD_  16
#define HB_  (NH_*B_)

// NORM * log2(e) folded into query projections so softmax uses raw ex2.
#define QSCALE 0.36067376022224085f

#define CHUNK 128
#define KSTR  20    // K smem row stride: conflict-free score-frag loads
#define VSTR  20    // V smem row stride: conflict-free for INTERLEAVED rows
                    // 2t / 2t+1 (shuffle-free PV; 24 would 2-way conflict)
#define XSTR  132   // x smem row stride in proj
#define BSTR  132   // Wcat smem row stride in proj

// ---------------- scratch (device globals; no allocation allowed) ----------
__device__ float g_Qtt[HB_*NT_*KD_];
__device__ float g_Qts[HB_*NT_*KD_];
__device__ float g_Kc [HB_*NT_*KD_];
__device__ float g_Vc [HB_*NT_*KD_];
__device__ float g_Qst[HB_*NS_*KD_];
__device__ float g_Ks [HB_*NS_*KD_];
__device__ float g_Vs [HB_*NS_*KD_];
__device__ float g_heads[B_*NN_*NH_*KD_];   // layout [b][n][h][k]

// ---------------- helpers ---------------------------------------------------
__device__ __forceinline__ ull pack2(float lo, float hi){
  ull r; asm("mov.b64 %0, {%1,%2};" : "=l"(r) : "f"(lo), "f"(hi)); return r;
}
__device__ __forceinline__ void unpack2(ull v, float& lo, float& hi){
  asm("mov.b64 {%0,%1}, %2;" : "=f"(lo), "=f"(hi) : "l"(v));
}
__device__ __forceinline__ ull ffma2(ull a, ull b, ull c){
  ull d; asm("fma.rn.f32x2 %0, %1, %2, %3;" : "=l"(d) : "l"(a), "l"(b), "l"(c)); return d;
}
__device__ __forceinline__ float ex2f(float x){
  float r; asm("ex2.approx.f32 %0, %1;" : "=f"(r) : "f"(x)); return r;
}
__device__ __forceinline__ uint32_t tf32r(float f){
  uint32_t u; asm("cvt.rna.tf32.f32 %0, %1;" : "=r"(u) : "f"(f)); return u;
}
__device__ __forceinline__ float tf32rf(float f){ return __uint_as_float(tf32r(f)); }

__device__ __forceinline__ void cp_async16(void* s, const void* g){
  unsigned sa = (unsigned)__cvta_generic_to_shared(s);
  asm volatile("cp.async.cg.shared.global [%0], [%1], 16;" :: "r"(sa), "l"(g));
}
__device__ __forceinline__ void cp_commit(){ asm volatile("cp.async.commit_group;"); }
template<int N> __device__ __forceinline__ void cp_wait(){
  asm volatile("cp.async.wait_group %0;" :: "n"(N) : "memory");
}

// tf32 MMA: D(16x8) += A(16x8,row) * B(8x8,col)
__device__ __forceinline__ void mma8(float& d0, float& d1, float& d2, float& d3,
    uint32_t a0, uint32_t a1, uint32_t a2, uint32_t a3, uint32_t b0, uint32_t b1)
{
  asm("mma.sync.aligned.m16n8k8.row.col.f32.tf32.tf32.f32 "
      "{%0,%1,%2,%3},{%4,%5,%6,%7},{%8,%9},{%0,%1,%2,%3};"
      : "+f"(d0), "+f"(d1), "+f"(d2), "+f"(d3)
      : "r"(a0), "r"(a1), "r"(a2), "r"(a3), "r"(b0), "r"(b1));
}

// Load Q A-fragments for 2 k-steps (head_dim 16). rA,rB pre-clamped row indices.
__device__ __forceinline__ void loadQ(const float* Qb, int rA, int rB, int tig,
                                      uint32_t a[2][4])
{
  #pragma unroll
  for (int ks = 0; ks < 2; ks++){
    a[ks][0] = __float_as_uint(Qb[(size_t)rA*KD_ + tig     + 8*ks]);
    a[ks][1] = __float_as_uint(Qb[(size_t)rB*KD_ + tig     + 8*ks]);
    a[ks][2] = __float_as_uint(Qb[(size_t)rA*KD_ + tig + 4 + 8*ks]);
    a[ks][3] = __float_as_uint(Qb[(size_t)rB*KD_ + tig + 4 + 8*ks]);
  }
}

// One 8-key step, SHUFFLE-FREE:
//   scores (2 MMA) -> exp -> (mask) -> cvt -> ones-MMA row sum -> P@V (2 MMA).
// The score D-frag is fed DIRECTLY as the PV A-frag with the within-lane
// register mapping (u0,u2,u1,u3): A-frag k-slot tig carries key 2*tig and slot
// tig+4 carries key 2*tig+1. V rows are read interleaved (2*tig, 2*tig+1) to
// match — a pure relabeling of the 8-key contraction (order-invariant).
// ls[0]=row g sum, ls[2]=row g+8 sum (ones-MMA fully reduces across the quad).
template<int MASK>
__device__ __forceinline__ void attn_step(
    const float* __restrict__ Ks, const float* __restrict__ Vs,
    const uint32_t (&aQ)[2][4], float (&o)[2][4], float (&ls)[4],
    int n8, int g, int tig, int lane, int nvalid)
{
  float c0 = 0.f, c1 = 0.f, c2 = 0.f, c3 = 0.f;
  const float* kp = Ks + (n8 + g)*KSTR + tig;
  {
    uint32_t b0 = __float_as_uint(kp[0]),  b1 = __float_as_uint(kp[4]);
    mma8(c0,c1,c2,c3, aQ[0][0],aQ[0][1],aQ[0][2],aQ[0][3], b0, b1);
    uint32_t b2 = __float_as_uint(kp[8]),  b3 = __float_as_uint(kp[12]);
    mma8(c0,c1,c2,c3, aQ[1][0],aQ[1][1],aQ[1][2],aQ[1][3], b2, b3);
  }
  float p0 = ex2f(c0), p1 = ex2f(c1), p2 = ex2f(c2), p3 = ex2f(c3);
  if (MASK){
    int col = n8 + tig*2;
    if (col     >= nvalid){ p0 = 0.f; p2 = 0.f; }
    if (col + 1 >= nvalid){ p1 = 0.f; p3 = 0.f; }
  }
  uint32_t u0 = tf32r(p0), u1 = tf32r(p1), u2 = tf32r(p2), u3 = tf32r(p3);
  const uint32_t one = 0x3f800000u;          // 1.0f (tf32-exact)
  mma8(ls[0], ls[1], ls[2], ls[3], u0, u2, u1, u3, one, one);
  const float* vp0 = Vs + (n8 + 2*tig    )*VSTR;
  const float* vp1 = Vs + (n8 + 2*tig + 1)*VSTR;
  #pragma unroll
  for (int nt = 0; nt < 2; nt++){
    uint32_t vb0 = __float_as_uint(vp0[nt*8 + g]);
    uint32_t vb1 = __float_as_uint(vp1[nt*8 + g]);
    mma8(o[nt][0], o[nt][1], o[nt][2], o[nt][3], u0, u2, u1, u3, vb0, vb1);
  }
}

// Cooperative chunk staging: 128 keys x 16 floats of K and V (256 threads).
__device__ __forceinline__ void stage_chunk(float* sKb, float* sVb,
    const float* __restrict__ Kg, const float* __restrict__ Vg, int kbase, int tid)
{
  #pragma unroll
  for (int i = 0; i < 2; i++){
    int f4  = tid + i*256;
    int row = f4 >> 2, qq = f4 & 3;
    int gr  = kbase + row;
    if (gr < NT_){
      cp_async16(sKb + row*KSTR + qq*4, Kg + (size_t)gr*KD_ + qq*4);
      cp_async16(sVb + row*VSTR + qq*4, Vg + (size_t)gr*KD_ + qq*4);
    }
  }
}

// ====================== Kernel 1: all projections ==========================
// blockIdx.x < 16 : token tile of 64 rows. Register-tiled fp32 f32x2 GEMM
//                   X[64,128] @ Wcat[128,128] per projection. W staged in two
//                   64-k halves -> smem 67.6KB -> 3 blocks/SM.
//                   Exact fp32 fma (tf32 proj FAILS rel-err: R7).
// blockIdx.x == 16: station projections (21 rows, scalar).
__global__ __launch_bounds__(256, 3) void k_proj(
    const float* __restrict__ q, const float* __restrict__ h,
    const float* __restrict__ Wqtt, const float* __restrict__ Wqts,
    const float* __restrict__ Wk, const float* __restrict__ Wv,
    const float* __restrict__ Wqst, const float* __restrict__ Wks,
    const float* __restrict__ Wvs)
{
  extern __shared__ float sm[];
  int b  = blockIdx.y;
  int tid = threadIdx.x;

  if (blockIdx.x == 16){
    float* sxq = sm;                 // 21*128
    float* sxh = sm + NS_*D_;
    float* sw  = sm + 2*NS_*D_;      // 128*16
    for (int idx = tid; idx < NS_*D_/4; idx += 256){
      int row = idx >> 5, d4 = idx & 31;
      size_t goff = ((size_t)(b*NN_ + row))*D_ + d4*4;
      ((float4*)sxq)[idx] = *(const float4*)(q + goff);
      ((float4*)sxh)[idx] = *(const float4*)(h + goff);
    }
    const float* Wp[3] = {Wqst, Wks, Wvs};
    for (int p = 0; p < 3; p++){
      const float* src = (p == 0) ? sxq : sxh;
      float scale = (p == 0) ? QSCALE : 1.0f;
      float* Dst = (p == 0) ? g_Qst : (p == 1 ? g_Ks : g_Vs);
      for (int hh = 0; hh < NH_; hh++){
        __syncthreads();
        const float* wp = Wp[p] + hh*D_*KD_;
        for (int idx = tid; idx < D_*KD_; idx += 256) sw[idx] = wp[idx]*scale;
        __syncthreads();
        for (int o = tid; o < NS_*KD_; o += 256){
          int s = o >> 4, k = o & 15;
          float a = 0.f;
          #pragma unroll 8
          for (int d = 0; d < D_; d++) a += src[s*D_ + d] * sw[d*KD_ + k];
          Dst[((size_t)(hh*B_ + b)*NS_ + s)*KD_ + k] = tf32rf(a);
        }
      }
    }
    return;
  }

  // ---------------- token projections: register-tiled GEMM ----------------
  float* sx = sm;                    // 64*XSTR   (x rows: q then h)
  float* sw = sm + 64*XSTR;          // 64*BSTR   (half of Wcat k-rows)

  int r0 = blockIdx.x * 64;
  int rg = tid >> 4, cg = tid & 15;            // 4-row group, 8-col group
  int hh = cg >> 1, khalf = (cg & 1)*8;

  const float* Xs[2] = {q, h};
  const float* Wp[4] = {Wqtt, Wqts, Wk, Wv};
  float* Dp[4]; Dp[0]=g_Qtt; Dp[1]=g_Qts; Dp[2]=g_Kc; Dp[3]=g_Vc;

  for (int ph = 0; ph < 2; ph++){
    const float* xs = Xs[ph];
    #pragma unroll
    for (int i = 0; i < 8; i++){
      int idx = tid + i*256;
      int row = idx >> 5, d4 = idx & 31;
      int t = r0 + row; if (t > NT_-1) t = NT_-1;
      ((float4*)(sx + row*XSTR))[d4] =
          *(const float4*)(xs + ((size_t)(b*NN_ + NS_ + t))*D_ + d4*4);
    }
    for (int pp = 0; pp < 2; pp++){
      int p = ph*2 + pp;
      float scale = (p < 2) ? QSCALE : 1.0f;
      const float* wg = Wp[p];

      ull acc[4][4];
      #pragma unroll
      for (int i = 0; i < 4; i++)
        #pragma unroll
        for (int j = 0; j < 4; j++) acc[i][j] = 0ull;

      for (int hf = 0; hf < 2; hf++){
        // stage this 64-k half of Wcat (grouped conflict-free layout)
        #pragma unroll
        for (int i = 0; i < 8; i++){
          int idx = tid + i*256;              // 2048 float4
          int d = idx & 63, hk = idx >> 6;
          int whh = hk >> 2, k4 = hk & 3;
          int dg = hf*64 + d;
          float4 v = *(const float4*)(wg + whh*(D_*KD_) + dg*KD_ + k4*4);
          v.x *= scale; v.y *= scale; v.z *= scale; v.w *= scale;
          *(float4*)(sw + d*BSTR + (k4 & 1)*64 + (whh*2 + (k4 >> 1))*4) = v;
        }
        __syncthreads();   // also covers x load (hf==0, pp==0)

        const float* Ab = sx + rg*4*XSTR + hf*64;
        const float* Bb = sw + cg*4;             // lane-contiguous 16B slots
        #pragma unroll 2
        for (int kg = 0; kg < 16; kg++){
          float4 a[4];
          #pragma unroll
          for (int i = 0; i < 4; i++)
            a[i] = *(const float4*)(Ab + i*XSTR + kg*4);
          #pragma unroll
          for (int kk = 0; kk < 4; kk++){
            ulonglong2 b0 = *(const ulonglong2*)(Bb + (kg*4 + kk)*BSTR);
            ulonglong2 b1 = *(const ulonglong2*)(Bb + (kg*4 + kk)*BSTR + 64);
            #pragma unroll
            for (int i = 0; i < 4; i++){
              float av = (&a[i].x)[kk];
              ull ap = pack2(av, av);
              acc[i][0] = ffma2(ap, b0.x, acc[i][0]);
              acc[i][1] = ffma2(ap, b0.y, acc[i][1]);
              acc[i][2] = ffma2(ap, b1.x, acc[i][2]);
              acc[i][3] = ffma2(ap, b1.y, acc[i][3]);
            }
          }
        }
        __syncthreads();   // before sw is overwritten (next half / next proj)
      }

      float* dst = Dp[p] + ((size_t)(hh*B_ + b))*NT_*KD_ + khalf;
      #pragma unroll
      for (int i = 0; i < 4; i++){
        int t = r0 + rg*4 + i;
        if (t < NT_){
          float f0,f1,f2,f3,f4,f5,f6,f7;
          unpack2(acc[i][0], f0, f1);
          unpack2(acc[i][1], f2, f3);
          unpack2(acc[i][2], f4, f5);
          unpack2(acc[i][3], f6, f7);
          float4 v0 = make_float4(tf32rf(f0), tf32rf(f1), tf32rf(f2), tf32rf(f3));
          float4 v1 = make_float4(tf32rf(f4), tf32rf(f5), tf32rf(f6), tf32rf(f7));
          *(float4*)(dst + (size_t)t*KD_)     = v0;
          *(float4*)(dst + (size_t)t*KD_ + 4) = v1;
        }
      }
    }
  }
}

// ====================== Kernel 2: all attention ============================
// blockIdx.x < 8 : token-query path (128-query tile, warp = 16 q x all keys).
// blockIdx.x == 8: station-query path (warp = 16 q-rows x key stripe).
// No online max (QSCALE folds NORM*log2e; scores bounded, raw ex2 safe).
// Shuffle-free P-frag relabeling (see attn_step); ones-MMA row sums.
__global__ __launch_bounds__(256, 3) void k_attn()
{
  extern __shared__ float dsm[];
  float* sK0 = dsm;                                   // [2][128*KSTR]
  float* sV0 = dsm + 2*CHUNK*KSTR;                    // [2][128*VSTR]
  float* sKs = dsm + 2*CHUNK*KSTR + 2*CHUNK*VSTR;     // token: [24*KSTR]
  float* sVs = sKs + 24*KSTR;                         // token: [24*VSTR]
  float* red = dsm + 2*CHUNK*KSTR + 2*CHUNK*VSTR;     // station: [8*32*10]

  int b = blockIdx.y, hh = blockIdx.z;
  int tid = threadIdx.x;
  int w = tid >> 5, lane = tid & 31;
  int g = lane >> 2, tig = lane & 3;
  size_t hb = (size_t)(hh*B_ + b);
  const float* Kg = g_Kc + hb*NT_*KD_;
  const float* Vg = g_Vc + hb*NT_*KD_;
  const int nch = (NT_ + CHUNK - 1)/CHUNK;   // 8

  if (blockIdx.x < 8){
    // ======== token-query path ========
    int qrow = blockIdx.x * 128 + w*16;
    int rA = min(qrow + g,     NT_-1);
    int rB = min(qrow + g + 8, NT_-1);

    // zero station pad rows (21..23) so pad scores are finite then masked
    for (int i = tid; i < 3*KSTR; i += 256) sKs[21*KSTR + i] = 0.f;
    for (int i = tid; i < 3*VSTR; i += 256) sVs[21*VSTR + i] = 0.f;
    // group 1: station K/V
    if (tid < 96){
      int row = tid >> 2, qq = tid & 3;
      if (row < NS_){
        cp_async16(sKs + row*KSTR + qq*4, g_Ks + (hb*NS_ + row)*KD_ + qq*4);
        cp_async16(sVs + row*VSTR + qq*4, g_Vs + (hb*NS_ + row)*KD_ + qq*4);
      }
    }
    cp_commit();
    // group 2: token chunk 0
    stage_chunk(sK0, sV0, Kg, Vg, 0, tid);
    cp_commit();

    uint32_t aT[2][4];
    loadQ(g_Qtt + hb*NT_*KD_, rA, rB, tig, aT);

    // ---- station prologue: full mini-softmax, normalized into os ----
    float os[2][4] = {{0,0,0,0},{0,0,0,0}};
    {
      uint32_t aS[2][4];
      loadQ(g_Qts + hb*NT_*KD_, rA, rB, tig, aS);
      cp_wait<1>();          // group 1 (station) done
      __syncthreads();
      float lsS[4] = {0,0,0,0};
      attn_step<0>(sKs, sVs, aS, os, lsS, 0,  g, tig, lane, 0);
      attn_step<0>(sKs, sVs, aS, os, lsS, 8,  g, tig, lane, 0);
      attn_step<1>(sKs, sVs, aS, os, lsS, 16, g, tig, lane, NS_);
      float isa = 1.f/lsS[0], isb = 1.f/lsS[2];
      #pragma unroll
      for (int nt = 0; nt < 2; nt++){
        os[nt][0] *= isa; os[nt][1] *= isa;
        os[nt][2] *= isb; os[nt][3] *= isb;
      }
    }

    // ---- token mainloop ----
    float ot[2][4] = {{0,0,0,0},{0,0,0,0}};
    float ls[4] = {0,0,0,0};
    for (int c = 0; c < nch; c++){
      if (c + 1 < nch){
        int nb = (c+1) & 1;
        stage_chunk(sK0 + nb*CHUNK*KSTR, sV0 + nb*CHUNK*VSTR, Kg, Vg, (c+1)*CHUNK, tid);
        cp_commit();
        cp_wait<1>();
      } else {
        cp_wait<0>();
      }
      __syncthreads();
      const float* Ks = sK0 + (c&1)*CHUNK*KSTR;
      const float* Vs = sV0 + (c&1)*CHUNK*VSTR;
      int nv = min(CHUNK, NT_ - c*CHUNK);
      int nf = nv >> 3;
      #pragma unroll 4
      for (int n = 0; n < nf; n++)
        attn_step<0>(Ks, Vs, aT, ot, ls, n*8, g, tig, lane, 0);
      if (nv & 7)
        attn_step<1>(Ks, Vs, aT, ot, ls, nf*8, g, tig, lane, nv);
      __syncthreads();
    }

    float ita = 1.f/ls[0], itb = 1.f/ls[2];   // ones-MMA: already full row sums
    int row0 = qrow + g, row1 = qrow + g + 8;
    #pragma unroll
    for (int nt = 0; nt < 2; nt++){
      if (row0 < NT_){
        float2 v; v.x = ot[nt][0]*ita + os[nt][0];
                  v.y = ot[nt][1]*ita + os[nt][1];
        *(float2*)(g_heads + ((size_t)(b*NN_ + NS_ + row0)*NH_ + hh)*KD_ + nt*8 + 2*tig) = v;
      }
      if (row1 < NT_){
        float2 v; v.x = ot[nt][2]*itb + os[nt][2];
                  v.y = ot[nt][3]*itb + os[nt][3];
        *(float2*)(g_heads + ((size_t)(b*NN_ + NS_ + row1)*NH_ + hh)*KD_ + nt*8 + 2*tig) = v;
      }
    }
  } else {
    // ======== station-query path ========
    int rt = w & 1, s = w >> 1;        // 2 q-row-tiles x 4 key stripes
    int rA = min(rt*16 + g,     NS_-1);
    int rB = min(rt*16 + g + 8, NS_-1);
    uint32_t aQ[2][4];
    loadQ(g_Qst + hb*NS_*KD_, rA, rB, tig, aQ);

    float o[2][4] = {{0,0,0,0},{0,0,0,0}};
    float ls[4] = {0,0,0,0};

    stage_chunk(sK0, sV0, Kg, Vg, 0, tid);
    cp_commit();
    for (int c = 0; c < nch; c++){
      if (c + 1 < nch){
        int nb = (c+1) & 1;
        stage_chunk(sK0 + nb*CHUNK*KSTR, sV0 + nb*CHUNK*VSTR, Kg, Vg, (c+1)*CHUNK, tid);
        cp_commit();
        cp_wait<1>();
      } else {
        cp_wait<0>();
      }
      __syncthreads();
      const float* Ks = sK0 + (c&1)*CHUNK*KSTR;
      const float* Vs = sV0 + (c&1)*CHUNK*VSTR;
      int nv = min(CHUNK, NT_ - c*CHUNK);
      #pragma unroll
      for (int j = 0; j < 4; j++){
        int n8 = (s*4 + j)*8;
        if (n8 + 8 <= nv)
          attn_step<0>(Ks, Vs, aQ, o, ls, n8, g, tig, lane, 0);
        else if (n8 < nv)
          attn_step<1>(Ks, Vs, aQ, o, ls, n8, g, tig, lane, nv);
      }
      __syncthreads();
    }

    float* rp = red + (w*32 + lane)*10;
    rp[0]=o[0][0]; rp[1]=o[0][1]; rp[2]=o[0][2]; rp[3]=o[0][3];
    rp[4]=o[1][0]; rp[5]=o[1][1]; rp[6]=o[1][2]; rp[7]=o[1][3];
    rp[8]=ls[0]; rp[9]=ls[2];
    __syncthreads();
    if (w < 2){
      float la = ls[0], lb = ls[2];
      #pragma unroll
      for (int ss = 1; ss < 4; ss++){
        float* qp = red + ((w + 2*ss)*32 + lane)*10;
        o[0][0]+=qp[0]; o[0][1]+=qp[1]; o[0][2]+=qp[2]; o[0][3]+=qp[3];
        o[1][0]+=qp[4]; o[1][1]+=qp[5]; o[1][2]+=qp[6]; o[1][3]+=qp[7];
        la += qp[8]; lb += qp[9];
      }
      float ia = 1.f/la, ib = 1.f/lb;
      int r0 = rt*16 + g, r1 = r0 + 8;
      #pragma unroll
      for (int nt = 0; nt < 2; nt++){
        if (r0 < NS_){
          float2 v; v.x = o[nt][0]*ia; v.y = o[nt][1]*ia;
          *(float2*)(g_heads + ((size_t)(b*NN_ + r0)*NH_ + hh)*KD_ + nt*8 + 2*tig) = v;
        }
        if (r1 < NS_){
          float2 v; v.x = o[nt][2]*ib; v.y = o[nt][3]*ib;
          *(float2*)(g_heads + ((size_t)(b*NN_ + r1)*NH_ + hh)*KD_ + nt*8 + 2*tig) = v;
        }
      }
    }
  }
}

// ================ Kernel 3: output GEMM (fp32 f32x2, value path) ===========
__global__ __launch_bounds__(256, 2) void k_out(
    const float* __restrict__ Wout, float* __restrict__ out)
{
  extern __shared__ float sm[];
  float* sA  = sm;              // 64*128
  float* sWt = sm + 64*D_;      // 128*132 transposed
  int m0 = blockIdx.x * 64;
  int tid = threadIdx.x;
  for (int idx = tid; idx < 64*32; idx += 256){
    int r = idx >> 5, d4 = idx & 31;
    ((float4*)(sA + r*D_))[d4] = ((const float4*)(g_heads + (size_t)(m0 + r)*D_))[d4];
  }
  for (int idx = tid; idx < D_*D_; idx += 256){
    int c = idx >> 7, e = idx & 127;
    sWt[e*132 + c] = Wout[idx];
  }
  __syncthreads();
  int rg = tid >> 4, cg = tid & 15;
  ull acc2[4][8];
  #pragma unroll
  for (int i = 0; i < 4; i++)
    #pragma unroll
    for (int e = 0; e < 8; e++) acc2[i][e] = 0ull;
  #pragma unroll 2
  for (int d4 = 0; d4 < 32; d4++){
    ulonglong2 a[4];
    #pragma unroll
    for (int i = 0; i < 4; i++)
      a[i] = *(const ulonglong2*)(sA + (rg*4 + i)*D_ + d4*4);
    #pragma unroll
    for (int e = 0; e < 8; e++){
      ulonglong2 wv = *(const ulonglong2*)(sWt + (cg*8 + e)*132 + d4*4);
      #pragma unroll
      for (int i = 0; i < 4; i++){
        acc2[i][e] = ffma2(a[i].x, wv.x, acc2[i][e]);
        acc2[i][e] = ffma2(a[i].y, wv.y, acc2[i][e]);
      }
    }
  }
  #pragma unroll
  for (int i = 0; i < 4; i++){
    #pragma unroll
    for (int e = 0; e < 8; e++){
      float lo, hi; unpack2(acc2[i][e], lo, hi);
      out[(size_t)(m0 + rg*4 + i)*D_ + cg*8 + e] = lo + hi;
    }
  }
}

// ===========================================================================
extern "C" void kernel_launch(void* const* d_in, const int* in_sizes, int n_in,
                              void* d_out, int out_size)
{
  const float* q     = (const float*)d_in[0];
  const float* h     = (const float*)d_in[1];
  const float* Wq_ts = (const float*)d_in[2];   // W_query_custom    -> Q_ts
  const float* Wq_tt = (const float*)d_in[3];   // W_query_custom_1  -> Q_tt
  const float* Wk_c  = (const float*)d_in[4];   // W_key_custom
  const float* Wv_c  = (const float*)d_in[5];   // W_val_custom
  const float* Wq_st = (const float*)d_in[6];   // W_query_charge_1  -> Q_st
  const float* Wk_s  = (const float*)d_in[7];   // W_key_charge
  const float* Wv_s  = (const float*)d_in[8];   // W_val_charge
  const float* Wout  = (const float*)d_in[9];
  float* out = (float*)d_out;

  int smem1 = (64*XSTR + 64*BSTR)*(int)sizeof(float);   // 67584 B -> 3 blk/SM
  cudaFuncSetAttribute(k_proj, cudaFuncAttributeMaxDynamicSharedMemorySize, smem1);
  int smemA = (2*CHUNK*KSTR + 2*CHUNK*VSTR + 8*32*10)*(int)sizeof(float);
  cudaFuncSetAttribute(k_attn, cudaFuncAttributeMaxDynamicSharedMemorySize, smemA);
  int smem5 = (64*D_ + D_*132)*(int)sizeof(float);
  cudaFuncSetAttribute(k_out, cudaFuncAttributeMaxDynamicSharedMemorySize, smem5);

  k_proj<<<dim3(17, 32), 256, smem1>>>(q, h, Wq_tt, Wq_ts, Wk_c, Wv_c,
                                       Wq_st, Wk_s, Wv_s);
  k_attn<<<dim3(9, 32, 8), 256, smemA>>>();
  k_out<<<512, 256, smem5>>>(Wout, out);
}

// round 17
// speedup vs baseline: 1.1866x; 1.0238x over previous
#include <cuda_runtime.h>
#include <cstdint>

typedef unsigned long long ull;

#define B_   32
#define NH_  8
#define NN_  1024
#define NS_  21
#define NT_  1003
#define D_   128
#define KD_  16
#define HB_  (NH_*B_)

// NORM * log2(e) folded into query projections so softmax uses raw ex2.
#define QSCALE 0.36067376022224085f

#define CHUNK 128
#define KSTR  20    // K smem row stride: conflict-free score-frag loads
#define VSTR  20    // V smem row stride: conflict-free for INTERLEAVED rows
                    // 2t / 2t+1 (shuffle-free PV)
#define XSTR  132   // x smem row stride in proj
#define BSTR  132   // Wcat smem row stride in proj

// ---------------- scratch (device globals; no allocation allowed) ----------
__device__ float g_Qtt[HB_*NT_*KD_];
__device__ float g_Qts[HB_*NT_*KD_];
__device__ float g_Kc [HB_*NT_*KD_];
__device__ float g_Vc [HB_*NT_*KD_];
__device__ float g_Qst[HB_*NS_*KD_];
__device__ float g_Ks [HB_*NS_*KD_];
__device__ float g_Vs [HB_*NS_*KD_];
__device__ float g_heads[B_*NN_*NH_*KD_];   // layout [b][n][h][k]

// ---------------- helpers ---------------------------------------------------
__device__ __forceinline__ ull pack2(float lo, float hi){
  ull r; asm("mov.b64 %0, {%1,%2};" : "=l"(r) : "f"(lo), "f"(hi)); return r;
}
__device__ __forceinline__ void unpack2(ull v, float& lo, float& hi){
  asm("mov.b64 {%0,%1}, %2;" : "=f"(lo), "=f"(hi) : "l"(v));
}
__device__ __forceinline__ ull ffma2(ull a, ull b, ull c){
  ull d; asm("fma.rn.f32x2 %0, %1, %2, %3;" : "=l"(d) : "l"(a), "l"(b), "l"(c)); return d;
}
__device__ __forceinline__ float ex2f(float x){
  float r; asm("ex2.approx.f32 %0, %1;" : "=f"(r) : "f"(x)); return r;
}
__device__ __forceinline__ uint32_t tf32r(float f){
  uint32_t u; asm("cvt.rna.tf32.f32 %0, %1;" : "=r"(u) : "f"(f)); return u;
}
__device__ __forceinline__ float tf32rf(float f){ return __uint_as_float(tf32r(f)); }

__device__ __forceinline__ void cp_async16(void* s, const void* g){
  unsigned sa = (unsigned)__cvta_generic_to_shared(s);
  asm volatile("cp.async.cg.shared.global [%0], [%1], 16;" :: "r"(sa), "l"(g));
}
__device__ __forceinline__ void cp_commit(){ asm volatile("cp.async.commit_group;"); }
template<int N> __device__ __forceinline__ void cp_wait(){
  asm volatile("cp.async.wait_group %0;" :: "n"(N) : "memory");
}

// tf32 MMA: D(16x8) += A(16x8,row) * B(8x8,col)
__device__ __forceinline__ void mma8(float& d0, float& d1, float& d2, float& d3,
    uint32_t a0, uint32_t a1, uint32_t a2, uint32_t a3, uint32_t b0, uint32_t b1)
{
  asm("mma.sync.aligned.m16n8k8.row.col.f32.tf32.tf32.f32 "
      "{%0,%1,%2,%3},{%4,%5,%6,%7},{%8,%9},{%0,%1,%2,%3};"
      : "+f"(d0), "+f"(d1), "+f"(d2), "+f"(d3)
      : "r"(a0), "r"(a1), "r"(a2), "r"(a3), "r"(b0), "r"(b1));
}

// Load Q A-fragments for 2 k-steps (head_dim 16). rA,rB pre-clamped row indices.
__device__ __forceinline__ void loadQ(const float* Qb, int rA, int rB, int tig,
                                      uint32_t a[2][4])
{
  #pragma unroll
  for (int ks = 0; ks < 2; ks++){
    a[ks][0] = __float_as_uint(Qb[(size_t)rA*KD_ + tig     + 8*ks]);
    a[ks][1] = __float_as_uint(Qb[(size_t)rB*KD_ + tig     + 8*ks]);
    a[ks][2] = __float_as_uint(Qb[(size_t)rA*KD_ + tig + 4 + 8*ks]);
    a[ks][3] = __float_as_uint(Qb[(size_t)rB*KD_ + tig + 4 + 8*ks]);
  }
}

// One 8-key step, SHUFFLE-FREE, NO ones-MMA:
//   scores (2 MMA) -> exp -> (mask) -> cvt -> FADD partial row sums ->
//   P@V (2 MMA, D-frag relabeled as A-frag within-lane: u0,u2,u1,u3 with
//   interleaved V rows 2*tig / 2*tig+1).
// la/lb hold PER-LANE partial sums of the tf32-rounded P (keys 2tig,2tig+1)
// for rows g / g+8 — quad butterfly (xor 1, xor 2) after the loop completes
// them. Sums the EXACT values the PV MMA consumes (consistent softmax).
template<int MASK>
__device__ __forceinline__ void attn_step(
    const float* __restrict__ Ks, const float* __restrict__ Vs,
    const uint32_t (&aQ)[2][4], float (&o)[2][4], float& la, float& lb,
    int n8, int g, int tig, int lane, int nvalid)
{
  float c0 = 0.f, c1 = 0.f, c2 = 0.f, c3 = 0.f;
  const float* kp = Ks + (n8 + g)*KSTR + tig;
  {
    uint32_t b0 = __float_as_uint(kp[0]),  b1 = __float_as_uint(kp[4]);
    mma8(c0,c1,c2,c3, aQ[0][0],aQ[0][1],aQ[0][2],aQ[0][3], b0, b1);
    uint32_t b2 = __float_as_uint(kp[8]),  b3 = __float_as_uint(kp[12]);
    mma8(c0,c1,c2,c3, aQ[1][0],aQ[1][1],aQ[1][2],aQ[1][3], b2, b3);
  }
  float p0 = ex2f(c0), p1 = ex2f(c1), p2 = ex2f(c2), p3 = ex2f(c3);
  if (MASK){
    int col = n8 + tig*2;
    if (col     >= nvalid){ p0 = 0.f; p2 = 0.f; }
    if (col + 1 >= nvalid){ p1 = 0.f; p3 = 0.f; }
  }
  uint32_t u0 = tf32r(p0), u1 = tf32r(p1), u2 = tf32r(p2), u3 = tf32r(p3);
  la += __uint_as_float(u0) + __uint_as_float(u1);
  lb += __uint_as_float(u2) + __uint_as_float(u3);
  const float* vp0 = Vs + (n8 + 2*tig    )*VSTR;
  const float* vp1 = Vs + (n8 + 2*tig + 1)*VSTR;
  #pragma unroll
  for (int nt = 0; nt < 2; nt++){
    uint32_t vb0 = __float_as_uint(vp0[nt*8 + g]);
    uint32_t vb1 = __float_as_uint(vp1[nt*8 + g]);
    mma8(o[nt][0], o[nt][1], o[nt][2], o[nt][3], u0, u2, u1, u3, vb0, vb1);
  }
}

// Quad butterfly: completes per-lane partial row sums across the 4 tig lanes.
__device__ __forceinline__ void quad_sum(float& v){
  v += __shfl_xor_sync(0xffffffffu, v, 1);
  v += __shfl_xor_sync(0xffffffffu, v, 2);
}

// Cooperative chunk staging: 128 keys x 16 floats of K and V (256 threads).
__device__ __forceinline__ void stage_chunk(float* sKb, float* sVb,
    const float* __restrict__ Kg, const float* __restrict__ Vg, int kbase, int tid)
{
  #pragma unroll
  for (int i = 0; i < 2; i++){
    int f4  = tid + i*256;
    int row = f4 >> 2, qq = f4 & 3;
    int gr  = kbase + row;
    if (gr < NT_){
      cp_async16(sKb + row*KSTR + qq*4, Kg + (size_t)gr*KD_ + qq*4);
      cp_async16(sVb + row*VSTR + qq*4, Vg + (size_t)gr*KD_ + qq*4);
    }
  }
}

// ====================== Kernel 1: all projections ==========================
// blockIdx.x < 16 : token tile of 64 rows. Register-tiled fp32 f32x2 GEMM
//                   X[64,128] @ Wcat[128,128] per projection. W staged in two
//                   64-k halves -> smem 67.6KB -> 3 blocks/SM.
//                   Exact fp32 fma (tf32 proj FAILS rel-err: R7).
// blockIdx.x == 16: station projections (21 rows, scalar).
__global__ __launch_bounds__(256, 3) void k_proj(
    const float* __restrict__ q, const float* __restrict__ h,
    const float* __restrict__ Wqtt, const float* __restrict__ Wqts,
    const float* __restrict__ Wk, const float* __restrict__ Wv,
    const float* __restrict__ Wqst, const float* __restrict__ Wks,
    const float* __restrict__ Wvs)
{
  extern __shared__ float sm[];
  int b  = blockIdx.y;
  int tid = threadIdx.x;

  if (blockIdx.x == 16){
    float* sxq = sm;                 // 21*128
    float* sxh = sm + NS_*D_;
    float* sw  = sm + 2*NS_*D_;      // 128*16
    for (int idx = tid; idx < NS_*D_/4; idx += 256){
      int row = idx >> 5, d4 = idx & 31;
      size_t goff = ((size_t)(b*NN_ + row))*D_ + d4*4;
      ((float4*)sxq)[idx] = *(const float4*)(q + goff);
      ((float4*)sxh)[idx] = *(const float4*)(h + goff);
    }
    const float* Wp[3] = {Wqst, Wks, Wvs};
    for (int p = 0; p < 3; p++){
      const float* src = (p == 0) ? sxq : sxh;
      float scale = (p == 0) ? QSCALE : 1.0f;
      float* Dst = (p == 0) ? g_Qst : (p == 1 ? g_Ks : g_Vs);
      for (int hh = 0; hh < NH_; hh++){
        __syncthreads();
        const float* wp = Wp[p] + hh*D_*KD_;
        for (int idx = tid; idx < D_*KD_; idx += 256) sw[idx] = wp[idx]*scale;
        __syncthreads();
        for (int o = tid; o < NS_*KD_; o += 256){
          int s = o >> 4, k = o & 15;
          float a = 0.f;
          #pragma unroll 8
          for (int d = 0; d < D_; d++) a += src[s*D_ + d] * sw[d*KD_ + k];
          Dst[((size_t)(hh*B_ + b)*NS_ + s)*KD_ + k] = tf32rf(a);
        }
      }
    }
    return;
  }

  // ---------------- token projections: register-tiled GEMM ----------------
  float* sx = sm;                    // 64*XSTR   (x rows: q then h)
  float* sw = sm + 64*XSTR;          // 64*BSTR   (half of Wcat k-rows)

  int r0 = blockIdx.x * 64;
  int rg = tid >> 4, cg = tid & 15;            // 4-row group, 8-col group
  int hh = cg >> 1, khalf = (cg & 1)*8;

  const float* Xs[2] = {q, h};
  const float* Wp[4] = {Wqtt, Wqts, Wk, Wv};
  float* Dp[4]; Dp[0]=g_Qtt; Dp[1]=g_Qts; Dp[2]=g_Kc; Dp[3]=g_Vc;

  for (int ph = 0; ph < 2; ph++){
    const float* xs = Xs[ph];
    #pragma unroll
    for (int i = 0; i < 8; i++){
      int idx = tid + i*256;
      int row = idx >> 5, d4 = idx & 31;
      int t = r0 + row; if (t > NT_-1) t = NT_-1;
      ((float4*)(sx + row*XSTR))[d4] =
          *(const float4*)(xs + ((size_t)(b*NN_ + NS_ + t))*D_ + d4*4);
    }
    for (int pp = 0; pp < 2; pp++){
      int p = ph*2 + pp;
      float scale = (p < 2) ? QSCALE : 1.0f;
      const float* wg = Wp[p];

      ull acc[4][4];
      #pragma unroll
      for (int i = 0; i < 4; i++)
        #pragma unroll
        for (int j = 0; j < 4; j++) acc[i][j] = 0ull;

      for (int hf = 0; hf < 2; hf++){
        // stage this 64-k half of Wcat (grouped conflict-free layout)
        #pragma unroll
        for (int i = 0; i < 8; i++){
          int idx = tid + i*256;              // 2048 float4
          int d = idx & 63, hk = idx >> 6;
          int whh = hk >> 2, k4 = hk & 3;
          int dg = hf*64 + d;
          float4 v = *(const float4*)(wg + whh*(D_*KD_) + dg*KD_ + k4*4);
          v.x *= scale; v.y *= scale; v.z *= scale; v.w *= scale;
          *(float4*)(sw + d*BSTR + (k4 & 1)*64 + (whh*2 + (k4 >> 1))*4) = v;
        }
        __syncthreads();   // also covers x load (hf==0, pp==0)

        const float* Ab = sx + rg*4*XSTR + hf*64;
        const float* Bb = sw + cg*4;             // lane-contiguous 16B slots
        #pragma unroll 2
        for (int kg = 0; kg < 16; kg++){
          float4 a[4];
          #pragma unroll
          for (int i = 0; i < 4; i++)
            a[i] = *(const float4*)(Ab + i*XSTR + kg*4);
          #pragma unroll
          for (int kk = 0; kk < 4; kk++){
            ulonglong2 b0 = *(const ulonglong2*)(Bb + (kg*4 + kk)*BSTR);
            ulonglong2 b1 = *(const ulonglong2*)(Bb + (kg*4 + kk)*BSTR + 64);
            #pragma unroll
            for (int i = 0; i < 4; i++){
              float av = (&a[i].x)[kk];
              ull ap = pack2(av, av);
              acc[i][0] = ffma2(ap, b0.x, acc[i][0]);
              acc[i][1] = ffma2(ap, b0.y, acc[i][1]);
              acc[i][2] = ffma2(ap, b1.x, acc[i][2]);
              acc[i][3] = ffma2(ap, b1.y, acc[i][3]);
            }
          }
        }
        __syncthreads();   // before sw is overwritten (next half / next proj)
      }

      float* dst = Dp[p] + ((size_t)(hh*B_ + b))*NT_*KD_ + khalf;
      #pragma unroll
      for (int i = 0; i < 4; i++){
        int t = r0 + rg*4 + i;
        if (t < NT_){
          float f0,f1,f2,f3,f4,f5,f6,f7;
          unpack2(acc[i][0], f0, f1);
          unpack2(acc[i][1], f2, f3);
          unpack2(acc[i][2], f4, f5);
          unpack2(acc[i][3], f6, f7);
          float4 v0 = make_float4(tf32rf(f0), tf32rf(f1), tf32rf(f2), tf32rf(f3));
          float4 v1 = make_float4(tf32rf(f4), tf32rf(f5), tf32rf(f6), tf32rf(f7));
          *(float4*)(dst + (size_t)t*KD_)     = v0;
          *(float4*)(dst + (size_t)t*KD_ + 4) = v1;
        }
      }
    }
  }
}

// ====================== Kernel 2: all attention ============================
// blockIdx.x < 8 : token-query path (128-query tile, warp = 16 q x all keys).
// blockIdx.x == 8: station-query path (warp = 16 q-rows x key stripe).
// No online max (QSCALE folds NORM*log2e; scores bounded, raw ex2 safe).
// Shuffle-free PV relabeling; FADD row sums (no ones-MMA: -20% tensor work);
// (256,4): 4 blocks/SM (smem 51.2KB x4 fits, regs capped 64) = 8 warps/SMSP.
__global__ __launch_bounds__(256, 4) void k_attn()
{
  extern __shared__ float dsm[];
  float* sK0 = dsm;                                   // [2][128*KSTR]
  float* sV0 = dsm + 2*CHUNK*KSTR;                    // [2][128*VSTR]
  float* sKs = dsm + 2*CHUNK*KSTR + 2*CHUNK*VSTR;     // token: [24*KSTR]
  float* sVs = sKs + 24*KSTR;                         // token: [24*VSTR]
  float* red = dsm + 2*CHUNK*KSTR + 2*CHUNK*VSTR;     // station: [8*32*10]

  int b = blockIdx.y, hh = blockIdx.z;
  int tid = threadIdx.x;
  int w = tid >> 5, lane = tid & 31;
  int g = lane >> 2, tig = lane & 3;
  size_t hb = (size_t)(hh*B_ + b);
  const float* Kg = g_Kc + hb*NT_*KD_;
  const float* Vg = g_Vc + hb*NT_*KD_;
  const int nch = (NT_ + CHUNK - 1)/CHUNK;   // 8

  if (blockIdx.x < 8){
    // ======== token-query path ========
    int qrow = blockIdx.x * 128 + w*16;
    int rA = min(qrow + g,     NT_-1);
    int rB = min(qrow + g + 8, NT_-1);

    // zero station pad rows (21..23) so pad scores are finite then masked
    for (int i = tid; i < 3*KSTR; i += 256) sKs[21*KSTR + i] = 0.f;
    for (int i = tid; i < 3*VSTR; i += 256) sVs[21*VSTR + i] = 0.f;
    // group 1: station K/V
    if (tid < 96){
      int row = tid >> 2, qq = tid & 3;
      if (row < NS_){
        cp_async16(sKs + row*KSTR + qq*4, g_Ks + (hb*NS_ + row)*KD_ + qq*4);
        cp_async16(sVs + row*VSTR + qq*4, g_Vs + (hb*NS_ + row)*KD_ + qq*4);
      }
    }
    cp_commit();
    // group 2: token chunk 0
    stage_chunk(sK0, sV0, Kg, Vg, 0, tid);
    cp_commit();

    uint32_t aT[2][4];
    loadQ(g_Qtt + hb*NT_*KD_, rA, rB, tig, aT);

    // ---- station prologue: full mini-softmax, normalized into os ----
    float os[2][4] = {{0,0,0,0},{0,0,0,0}};
    {
      uint32_t aS[2][4];
      loadQ(g_Qts + hb*NT_*KD_, rA, rB, tig, aS);
      cp_wait<1>();          // group 1 (station) done
      __syncthreads();
      float lsa = 0.f, lsb = 0.f;
      attn_step<0>(sKs, sVs, aS, os, lsa, lsb, 0,  g, tig, lane, 0);
      attn_step<0>(sKs, sVs, aS, os, lsa, lsb, 8,  g, tig, lane, 0);
      attn_step<1>(sKs, sVs, aS, os, lsa, lsb, 16, g, tig, lane, NS_);
      quad_sum(lsa); quad_sum(lsb);
      float isa = 1.f/lsa, isb = 1.f/lsb;
      #pragma unroll
      for (int nt = 0; nt < 2; nt++){
        os[nt][0] *= isa; os[nt][1] *= isa;
        os[nt][2] *= isb; os[nt][3] *= isb;
      }
    }

    // ---- token mainloop ----
    float ot[2][4] = {{0,0,0,0},{0,0,0,0}};
    float lta = 0.f, ltb = 0.f;
    for (int c = 0; c < nch; c++){
      if (c + 1 < nch){
        int nb = (c+1) & 1;
        stage_chunk(sK0 + nb*CHUNK*KSTR, sV0 + nb*CHUNK*VSTR, Kg, Vg, (c+1)*CHUNK, tid);
        cp_commit();
        cp_wait<1>();
      } else {
        cp_wait<0>();
      }
      __syncthreads();
      const float* Ks = sK0 + (c&1)*CHUNK*KSTR;
      const float* Vs = sV0 + (c&1)*CHUNK*VSTR;
      int nv = min(CHUNK, NT_ - c*CHUNK);
      int nf = nv >> 3;
      #pragma unroll 4
      for (int n = 0; n < nf; n++)
        attn_step<0>(Ks, Vs, aT, ot, lta, ltb, n*8, g, tig, lane, 0);
      if (nv & 7)
        attn_step<1>(Ks, Vs, aT, ot, lta, ltb, nf*8, g, tig, lane, nv);
      __syncthreads();
    }

    quad_sum(lta); quad_sum(ltb);
    float ita = 1.f/lta, itb = 1.f/ltb;
    int row0 = qrow + g, row1 = qrow + g + 8;
    #pragma unroll
    for (int nt = 0; nt < 2; nt++){
      if (row0 < NT_){
        float2 v; v.x = ot[nt][0]*ita + os[nt][0];
                  v.y = ot[nt][1]*ita + os[nt][1];
        *(float2*)(g_heads + ((size_t)(b*NN_ + NS_ + row0)*NH_ + hh)*KD_ + nt*8 + 2*tig) = v;
      }
      if (row1 < NT_){
        float2 v; v.x = ot[nt][2]*itb + os[nt][2];
                  v.y = ot[nt][3]*itb + os[nt][3];
        *(float2*)(g_heads + ((size_t)(b*NN_ + NS_ + row1)*NH_ + hh)*KD_ + nt*8 + 2*tig) = v;
      }
    }
  } else {
    // ======== station-query path ========
    int rt = w & 1, s = w >> 1;        // 2 q-row-tiles x 4 key stripes
    int rA = min(rt*16 + g,     NS_-1);
    int rB = min(rt*16 + g + 8, NS_-1);
    uint32_t aQ[2][4];
    loadQ(g_Qst + hb*NS_*KD_, rA, rB, tig, aQ);

    float o[2][4] = {{0,0,0,0},{0,0,0,0}};
    float la = 0.f, lb = 0.f;

    stage_chunk(sK0, sV0, Kg, Vg, 0, tid);
    cp_commit();
    for (int c = 0; c < nch; c++){
      if (c + 1 < nch){
        int nb = (c+1) & 1;
        stage_chunk(sK0 + nb*CHUNK*KSTR, sV0 + nb*CHUNK*VSTR, Kg, Vg, (c+1)*CHUNK, tid);
        cp_commit();
        cp_wait<1>();
      } else {
        cp_wait<0>();
      }
      __syncthreads();
      const float* Ks = sK0 + (c&1)*CHUNK*KSTR;
      const float* Vs = sV0 + (c&1)*CHUNK*VSTR;
      int nv = min(CHUNK, NT_ - c*CHUNK);
      #pragma unroll
      for (int j = 0; j < 4; j++){
        int n8 = (s*4 + j)*8;
        if (n8 + 8 <= nv)
          attn_step<0>(Ks, Vs, aQ, o, la, lb, n8, g, tig, lane, 0);
        else if (n8 < nv)
          attn_step<1>(Ks, Vs, aQ, o, la, lb, n8, g, tig, lane, nv);
      }
      __syncthreads();
    }

    // complete row sums within the quad before the cross-warp reduction
    quad_sum(la); quad_sum(lb);
    float* rp = red + (w*32 + lane)*10;
    rp[0]=o[0][0]; rp[1]=o[0][1]; rp[2]=o[0][2]; rp[3]=o[0][3];
    rp[4]=o[1][0]; rp[5]=o[1][1]; rp[6]=o[1][2]; rp[7]=o[1][3];
    rp[8]=la; rp[9]=lb;
    __syncthreads();
    if (w < 2){
      #pragma unroll
      for (int ss = 1; ss < 4; ss++){
        float* qp = red + ((w + 2*ss)*32 + lane)*10;
        o[0][0]+=qp[0]; o[0][1]+=qp[1]; o[0][2]+=qp[2]; o[0][3]+=qp[3];
        o[1][0]+=qp[4]; o[1][1]+=qp[5]; o[1][2]+=qp[6]; o[1][3]+=qp[7];
        la += qp[8]; lb += qp[9];
      }
      float ia = 1.f/la, ib = 1.f/lb;
      int r0 = rt*16 + g, r1 = r0 + 8;
      #pragma unroll
      for (int nt = 0; nt < 2; nt++){
        if (r0 < NS_){
          float2 v; v.x = o[nt][0]*ia; v.y = o[nt][1]*ia;
          *(float2*)(g_heads + ((size_t)(b*NN_ + r0)*NH_ + hh)*KD_ + nt*8 + 2*tig) = v;
        }
        if (r1 < NS_){
          float2 v; v.x = o[nt][2]*ib; v.y = o[nt][3]*ib;
          *(float2*)(g_heads + ((size_t)(b*NN_ + r1)*NH_ + hh)*KD_ + nt*8 + 2*tig) = v;
        }
      }
    }
  }
}

// ================ Kernel 3: output GEMM (fp32 f32x2, value path) ===========
__global__ __launch_bounds__(256, 2) void k_out(
    const float* __restrict__ Wout, float* __restrict__ out)
{
  extern __shared__ float sm[];
  float* sA  = sm;              // 64*128
  float* sWt = sm + 64*D_;      // 128*132 transposed
  int m0 = blockIdx.x * 64;
  int tid = threadIdx.x;
  for (int idx = tid; idx < 64*32; idx += 256){
    int r = idx >> 5, d4 = idx & 31;
    ((float4*)(sA + r*D_))[d4] = ((const float4*)(g_heads + (size_t)(m0 + r)*D_))[d4];
  }
  for (int idx = tid; idx < D_*D_; idx += 256){
    int c = idx >> 7, e = idx & 127;
    sWt[e*132 + c] = Wout[idx];
  }
  __syncthreads();
  int rg = tid >> 4, cg = tid & 15;
  ull acc2[4][8];
  #pragma unroll
  for (int i = 0; i < 4; i++)
    #pragma unroll
    for (int e = 0; e < 8; e++) acc2[i][e] = 0ull;
  #pragma unroll 2
  for (int d4 = 0; d4 < 32; d4++){
    ulonglong2 a[4];
    #pragma unroll
    for (int i = 0; i < 4; i++)
      a[i] = *(const ulonglong2*)(sA + (rg*4 + i)*D_ + d4*4);
    #pragma unroll
    for (int e = 0; e < 8; e++){
      ulonglong2 wv = *(const ulonglong2*)(sWt + (cg*8 + e)*132 + d4*4);
      #pragma unroll
      for (int i = 0; i < 4; i++){
        acc2[i][e] = ffma2(a[i].x, wv.x, acc2[i][e]);
        acc2[i][e] = ffma2(a[i].y, wv.y, acc2[i][e]);
      }
    }
  }
  #pragma unroll
  for (int i = 0; i < 4; i++){
    #pragma unroll
    for (int e = 0; e < 8; e++){
      float lo, hi; unpack2(acc2[i][e], lo, hi);
      out[(size_t)(m0 + rg*4 + i)*D_ + cg*8 + e] = lo + hi;
    }
  }
}

// ===========================================================================
extern "C" void kernel_launch(void* const* d_in, const int* in_sizes, int n_in,
                              void* d_out, int out_size)
{
  const float* q     = (const float*)d_in[0];
  const float* h     = (const float*)d_in[1];
  const float* Wq_ts = (const float*)d_in[2];   // W_query_custom    -> Q_ts
  const float* Wq_tt = (const float*)d_in[3];   // W_query_custom_1  -> Q_tt
  const float* Wk_c  = (const float*)d_in[4];   // W_key_custom
  const float* Wv_c  = (const float*)d_in[5];   // W_val_custom
  const float* Wq_st = (const float*)d_in[6];   // W_query_charge_1  -> Q_st
  const float* Wk_s  = (const float*)d_in[7];   // W_key_charge
  const float* Wv_s  = (const float*)d_in[8];   // W_val_charge
  const float* Wout  = (const float*)d_in[9];
  float* out = (float*)d_out;

  int smem1 = (64*XSTR + 64*BSTR)*(int)sizeof(float);   // 67584 B -> 3 blk/SM
  cudaFuncSetAttribute(k_proj, cudaFuncAttributeMaxDynamicSharedMemorySize, smem1);
  int smemA = (2*CHUNK*KSTR + 2*CHUNK*VSTR + 8*32*10)*(int)sizeof(float);
  cudaFuncSetAttribute(k_attn, cudaFuncAttributeMaxDynamicSharedMemorySize, smemA);
  int smem5 = (64*D_ + D_*132)*(int)sizeof(float);
  cudaFuncSetAttribute(k_out, cudaFuncAttributeMaxDynamicSharedMemorySize, smem5);

  k_proj<<<dim3(17, 32), 256, smem1>>>(q, h, Wq_tt, Wq_ts, Wk_c, Wv_c,
                                       Wq_st, Wk_s, Wv_s);
  k_attn<<<dim3(9, 32, 8), 256, smemA>>>();
  k_out<<<512, 256, smem5>>>(Wout, out);
}